// round 3
// baseline (speedup 1.0000x reference)
#include <cuda_runtime.h>
#include <math.h>

#define D 128
#define MAX_N_STU 100000
#define MAX_N_ITEM 20000
#define MAX_E_R 500000
#define MAX_E_P 300000
#define SA_STRIDE 132  // 128 + 4 pad: conflict-free fragment LDS

// ---------------- scratch (device globals; no allocation allowed) ------------
__device__ float g_mean_item[(size_t)MAX_N_ITEM * D];
__device__ float g_mean_stu[(size_t)MAX_N_STU * D];
__device__ float g_R[(size_t)MAX_N_STU * D];
__device__ float g_Q[(size_t)MAX_N_STU * D];
__device__ float g_Hmean[(size_t)MAX_N_STU * D];
__device__ float g_stats[4 * D];  // itemSum | itemSS | stuSum | stuSS

// CSR scratch
__device__ int g_deg_item[MAX_N_ITEM];
__device__ int g_rp_item[MAX_N_ITEM + 1];
__device__ int g_cur_item[MAX_N_ITEM];
__device__ int g_adj_item[MAX_E_R];
__device__ int g_deg_rs[MAX_N_STU];
__device__ int g_rp_rs[MAX_N_STU + 1];
__device__ int g_cur_rs[MAX_N_STU];
__device__ int g_adj_rs[MAX_E_R];
__device__ int g_deg_p[MAX_N_STU];
__device__ int g_rp_p[MAX_N_STU + 1];
__device__ int g_cur_p[MAX_N_STU];
__device__ int g_adj_p[MAX_E_P];

// ---------------- small zero --------------------------------------------------
__global__ void zero_small_kernel() {
    int i = blockIdx.x * blockDim.x + threadIdx.x;
    int stride = gridDim.x * blockDim.x;
    for (int x = i; x < MAX_N_STU; x += stride) {
        g_deg_rs[x] = 0;
        g_deg_p[x] = 0;
        if (x < MAX_N_ITEM) g_deg_item[x] = 0;
        if (x < 4 * D) g_stats[x] = 0.f;
    }
}

// ---------------- CSR build ---------------------------------------------------
__global__ void hist_kernel(const int* __restrict__ rsrc, const int* __restrict__ rdst,
                            int eR, const int* __restrict__ pdst, int eP) {
    int i = blockIdx.x * blockDim.x + threadIdx.x;
    if (i < eR) {
        atomicAdd(&g_deg_item[rdst[i]], 1);
        atomicAdd(&g_deg_rs[rsrc[i]], 1);
    }
    if (i < eP) atomicAdd(&g_deg_p[pdst[i]], 1);
}

__global__ __launch_bounds__(1024) void scan3_kernel(int n_item, int n_stu) {
    int n;
    int *deg, *rp, *cur;
    if (blockIdx.x == 0) { n = n_item; deg = g_deg_item; rp = g_rp_item; cur = g_cur_item; }
    else if (blockIdx.x == 1) { n = n_stu; deg = g_deg_rs; rp = g_rp_rs; cur = g_cur_rs; }
    else { n = n_stu; deg = g_deg_p; rp = g_rp_p; cur = g_cur_p; }

    __shared__ int warpSums[32];
    int chunk = (n + 1023) >> 10;
    int begin = min((int)threadIdx.x * chunk, n);
    int end = min(begin + chunk, n);
    int s = 0;
    for (int i = begin; i < end; i++) s += deg[i];
    int lane = threadIdx.x & 31, w = threadIdx.x >> 5;
    int v = s;
#pragma unroll
    for (int o = 1; o < 32; o <<= 1) {
        int t = __shfl_up_sync(0xffffffffu, v, o);
        if (lane >= o) v += t;
    }
    if (lane == 31) warpSums[w] = v;
    __syncthreads();
    if (w == 0) {
        int t = warpSums[lane];
#pragma unroll
        for (int o = 1; o < 32; o <<= 1) {
            int u = __shfl_up_sync(0xffffffffu, t, o);
            if (lane >= o) t += u;
        }
        warpSums[lane] = t;
    }
    __syncthreads();
    int excl = v - s + (w > 0 ? warpSums[w - 1] : 0);
    int run = excl;
    for (int i = begin; i < end; i++) {
        rp[i] = run;
        cur[i] = run;
        run += deg[i];
    }
    if (begin < n && end == n) rp[n] = run;
}

__global__ void fill_kernel(const int* __restrict__ rsrc, const int* __restrict__ rdst,
                            int eR, const int* __restrict__ psrc,
                            const int* __restrict__ pdst, int eP) {
    int i = blockIdx.x * blockDim.x + threadIdx.x;
    if (i < eR) {
        int s = rsrc[i], d = rdst[i];
        g_adj_item[atomicAdd(&g_cur_item[d], 1)] = s;
        g_adj_rs[atomicAdd(&g_cur_rs[s], 1)] = d;
    }
    if (i < eP) {
        g_adj_p[atomicAdd(&g_cur_p[pdst[i]], 1)] = psrc[i];
    }
}

// ---------------- CSR aggregation (warp per node, gather) ----------------------
__global__ void agg_csr_kernel(const float* __restrict__ X,
                               const int* __restrict__ rp,
                               const int* __restrict__ adj,
                               float* __restrict__ out, int N) {
    int node = (blockIdx.x * blockDim.x + threadIdx.x) >> 5;
    if (node >= N) return;
    int lane = threadIdx.x & 31;
    int b = rp[node], e = rp[node + 1];
    float4 acc = make_float4(0.f, 0.f, 0.f, 0.f);
    for (int base = b; base < e; base += 32) {
        int nb = min(32, e - base);
        int myAdj = (lane < nb) ? adj[base + lane] : 0;
        for (int j = 0; j < nb; j++) {
            int s = __shfl_sync(0xffffffffu, myAdj, j);
            float4 v = ((const float4*)(X + (size_t)s * D))[lane];
            acc.x += v.x; acc.y += v.y; acc.z += v.z; acc.w += v.w;
        }
    }
    float inv = 1.f / (float)max(e - b, 1);
    acc.x *= inv; acc.y *= inv; acc.z *= inv; acc.w *= inv;
    ((float4*)(out + (size_t)node * D))[lane] = acc;
}

__device__ __forceinline__ float elu1(float x) {
    return x > 0.f ? x : expm1f(x);
}

// Hmean[d] = mean_e elu(R[src] + Q[d] + b1)
__global__ void simple_csr_kernel(const float* __restrict__ R,
                                  const float* __restrict__ Q,
                                  const float* __restrict__ b1,
                                  const int* __restrict__ rp,
                                  const int* __restrict__ adj,
                                  float* __restrict__ Hmean, int N) {
    int node = (blockIdx.x * blockDim.x + threadIdx.x) >> 5;
    if (node >= N) return;
    int lane = threadIdx.x & 31;
    int b = rp[node], e = rp[node + 1];
    float4 qd = ((const float4*)(Q + (size_t)node * D))[lane];
    float4 bb = ((const float4*)b1)[lane];
    qd.x += bb.x; qd.y += bb.y; qd.z += bb.z; qd.w += bb.w;
    float4 acc = make_float4(0.f, 0.f, 0.f, 0.f);
    for (int base = b; base < e; base += 32) {
        int nb = min(32, e - base);
        int myAdj = (lane < nb) ? adj[base + lane] : 0;
        for (int j = 0; j < nb; j++) {
            int s = __shfl_sync(0xffffffffu, myAdj, j);
            float4 r = ((const float4*)(R + (size_t)s * D))[lane];
            acc.x += elu1(r.x + qd.x);
            acc.y += elu1(r.y + qd.y);
            acc.z += elu1(r.z + qd.z);
            acc.w += elu1(r.w + qd.w);
        }
    }
    float inv = 1.f / (float)max(e - b, 1);
    acc.x *= inv; acc.y *= inv; acc.z *= inv; acc.w *= inv;
    ((float4*)(Hmean + (size_t)node * D))[lane] = acc;
}

// ---------------- tensor-core GEMM pieces (tf32 mma.sync) ---------------------
__device__ __forceinline__ unsigned f2tf(float x) {
    unsigned r;
    asm("cvt.rna.tf32.f32 %0, %1;" : "=r"(r) : "f"(x));
    return r;
}

__device__ __forceinline__ void stage_A(const float* __restrict__ A, int M,
                                        int rowBase, unsigned* sA) {
    for (int i = threadIdx.x; i < 128 * 32; i += 256) {
        int r = i >> 5, c4 = (i & 31) * 4;
        int gr = rowBase + r;
        float4 v = make_float4(0.f, 0.f, 0.f, 0.f);
        if (gr < M) v = ((const float4*)(A + (size_t)gr * D))[c4 >> 2];
        unsigned* p = sA + r * SA_STRIDE + c4;
        p[0] = f2tf(v.x); p[1] = f2tf(v.y); p[2] = f2tf(v.z); p[3] = f2tf(v.w);
    }
}

__device__ __forceinline__ void stage_Wt(const float* __restrict__ W, unsigned* sW) {
    for (int i = threadIdx.x; i < 128 * 32; i += 256) {
        int k = i & 127, n4 = i >> 7;
        float4 v = ((const float4*)(W + (size_t)k * D))[n4];
        sW[(n4 * 4 + 0) * SA_STRIDE + k] = f2tf(v.x);
        sW[(n4 * 4 + 1) * SA_STRIDE + k] = f2tf(v.y);
        sW[(n4 * 4 + 2) * SA_STRIDE + k] = f2tf(v.z);
        sW[(n4 * 4 + 3) * SA_STRIDE + k] = f2tf(v.w);
    }
}

// stage (Wa - Wb) transposed
__device__ __forceinline__ void stage_Wt_diff(const float* __restrict__ Wa,
                                              const float* __restrict__ Wb,
                                              unsigned* sW) {
    for (int i = threadIdx.x; i < 128 * 32; i += 256) {
        int k = i & 127, n4 = i >> 7;
        float4 a = ((const float4*)(Wa + (size_t)k * D))[n4];
        float4 b = ((const float4*)(Wb + (size_t)k * D))[n4];
        sW[(n4 * 4 + 0) * SA_STRIDE + k] = f2tf(a.x - b.x);
        sW[(n4 * 4 + 1) * SA_STRIDE + k] = f2tf(a.y - b.y);
        sW[(n4 * 4 + 2) * SA_STRIDE + k] = f2tf(a.z - b.z);
        sW[(n4 * 4 + 3) * SA_STRIDE + k] = f2tf(a.w - b.w);
    }
}

__device__ __forceinline__ void mm_tc(const unsigned* sA, const unsigned* sW,
                                      float acc[16][4]) {
    int lane = threadIdx.x & 31, w = threadIdx.x >> 5;
    int g = lane >> 2, t = lane & 3;
    const unsigned* Abase = sA + (w * 16 + g) * SA_STRIDE + t;
#pragma unroll
    for (int k0 = 0; k0 < 128; k0 += 8) {
        unsigned a0 = Abase[k0];
        unsigned a1 = Abase[8 * SA_STRIDE + k0];
        unsigned a2 = Abase[k0 + 4];
        unsigned a3 = Abase[8 * SA_STRIDE + k0 + 4];
        const unsigned* Bk = sW + g * SA_STRIDE + k0 + t;
#pragma unroll
        for (int j = 0; j < 16; j++) {
            unsigned b0 = Bk[8 * j * SA_STRIDE];
            unsigned b1 = Bk[8 * j * SA_STRIDE + 4];
            asm volatile(
                "mma.sync.aligned.m16n8k8.row.col.f32.tf32.tf32.f32 "
                "{%0,%1,%2,%3},{%4,%5,%6,%7},{%8,%9},{%0,%1,%2,%3};"
                : "+f"(acc[j][0]), "+f"(acc[j][1]), "+f"(acc[j][2]), "+f"(acc[j][3])
                : "r"(a0), "r"(a1), "r"(a2), "r"(a3), "r"(b0), "r"(b1));
        }
    }
}

// R = x@(W1top - W1bot), Q = x@W1bot; shares the staged A tile.
__global__ __launch_bounds__(256) void gemm_rq_tc(const float* __restrict__ x,
                                                  const float* __restrict__ W1,
                                                  float* __restrict__ Rm,
                                                  float* __restrict__ Qm, int M) {
    extern __shared__ unsigned smem_u[];
    unsigned* sA = smem_u;
    unsigned* sW = smem_u + 128 * SA_STRIDE;
    int rowBase = blockIdx.x * 128;
    int lane = threadIdx.x & 31, w = threadIdx.x >> 5;
    int g = lane >> 2, t = lane & 3;
    int r0 = rowBase + w * 16 + g, r1 = r0 + 8;

    stage_A(x, M, rowBase, sA);
    stage_Wt(W1 + 128 * D, sW);
    __syncthreads();
    {
        float acc[16][4] = {};
        mm_tc(sA, sW, acc);
#pragma unroll
        for (int j = 0; j < 16; j++) {
            int c = 8 * j + 2 * t;
            if (r0 < M) *(float2*)(Qm + (size_t)r0 * D + c) = make_float2(acc[j][0], acc[j][1]);
            if (r1 < M) *(float2*)(Qm + (size_t)r1 * D + c) = make_float2(acc[j][2], acc[j][3]);
        }
    }
    __syncthreads();
    stage_Wt_diff(W1, W1 + 128 * D, sW);
    __syncthreads();
    {
        float acc[16][4] = {};
        mm_tc(sA, sW, acc);
#pragma unroll
        for (int j = 0; j < 16; j++) {
            int c = 8 * j + 2 * t;
            if (r0 < M) *(float2*)(Rm + (size_t)r0 * D + c) = make_float2(acc[j][0], acc[j][1]);
            if (r1 < M) *(float2*)(Rm + (size_t)r1 * D + c) = make_float2(acc[j][2], acc[j][3]);
        }
    }
}

// item_out_pre_bn = elu( meanI@Wl + x_item@Wr + b ) -> out
__global__ __launch_bounds__(256) void out_item_tc(
    const float* __restrict__ meanI, const float* __restrict__ x_item,
    const float* __restrict__ Wl, const float* __restrict__ Wr,
    const float* __restrict__ b, float* __restrict__ out, int M) {
    extern __shared__ unsigned smem_u[];
    unsigned* sA = smem_u;
    unsigned* sW = smem_u + 128 * SA_STRIDE;
    int rowBase = blockIdx.x * 128;
    float acc[16][4] = {};

    stage_A(meanI, M, rowBase, sA);
    stage_Wt(Wl, sW);
    __syncthreads();
    mm_tc(sA, sW, acc);
    __syncthreads();
    stage_A(x_item, M, rowBase, sA);
    stage_Wt(Wr, sW);
    __syncthreads();
    mm_tc(sA, sW, acc);

    int lane = threadIdx.x & 31, w = threadIdx.x >> 5;
    int g = lane >> 2, t = lane & 3;
    int r0 = rowBase + w * 16 + g, r1 = r0 + 8;
#pragma unroll
    for (int j = 0; j < 16; j++) {
        int c = 8 * j + 2 * t;
        float b0v = b[c], b1v = b[c + 1];
        if (r0 < M)
            *(float2*)(out + (size_t)r0 * D + c) =
                make_float2(elu1(acc[j][0] + b0v), elu1(acc[j][1] + b1v));
        if (r1 < M)
            *(float2*)(out + (size_t)r1 * D + c) =
                make_float2(elu1(acc[j][2] + b0v), elu1(acc[j][3] + b1v));
    }
}

// stu_out_pre_bn = elu( 0.5*( meanS@Wl + x@Wr + b_st + Hmean@W2 + [deg>0]*b2 ) )
__global__ __launch_bounds__(256) void out_stu_tc(
    const float* __restrict__ meanS, const float* __restrict__ x_stu,
    const float* __restrict__ Hmean, const int* __restrict__ rp_p,
    const float* __restrict__ Wl, const float* __restrict__ Wr,
    const float* __restrict__ W2, const float* __restrict__ b_st,
    const float* __restrict__ b2, float* __restrict__ out, int M) {
    extern __shared__ unsigned smem_u[];
    unsigned* sA = smem_u;
    unsigned* sW = smem_u + 128 * SA_STRIDE;
    int rowBase = blockIdx.x * 128;
    float acc[16][4] = {};

    stage_A(meanS, M, rowBase, sA);
    stage_Wt(Wl, sW);
    __syncthreads();
    mm_tc(sA, sW, acc);
    __syncthreads();
    stage_A(x_stu, M, rowBase, sA);
    stage_Wt(Wr, sW);
    __syncthreads();
    mm_tc(sA, sW, acc);
    __syncthreads();
    stage_A(Hmean, M, rowBase, sA);
    stage_Wt(W2, sW);
    __syncthreads();
    mm_tc(sA, sW, acc);

    int lane = threadIdx.x & 31, w = threadIdx.x >> 5;
    int g = lane >> 2, t = lane & 3;
    int r0 = rowBase + w * 16 + g, r1 = r0 + 8;
    float hasP0 = (r0 < M && rp_p[r0 + 1] > rp_p[r0]) ? 1.f : 0.f;
    float hasP1 = (r1 < M && rp_p[r1 + 1] > rp_p[r1]) ? 1.f : 0.f;
#pragma unroll
    for (int j = 0; j < 16; j++) {
        int c = 8 * j + 2 * t;
        float bs0 = b_st[c], bs1 = b_st[c + 1];
        float b20 = b2[c], b21 = b2[c + 1];
        if (r0 < M)
            *(float2*)(out + (size_t)r0 * D + c) = make_float2(
                elu1(0.5f * (acc[j][0] + bs0 + hasP0 * b20)),
                elu1(0.5f * (acc[j][1] + bs1 + hasP0 * b21)));
        if (r1 < M)
            *(float2*)(out + (size_t)r1 * D + c) = make_float2(
                elu1(0.5f * (acc[j][2] + bs0 + hasP1 * b20)),
                elu1(0.5f * (acc[j][3] + bs1 + hasP1 * b21)));
    }
}

// ---------------- BN stats + finalize -----------------------------------------
__global__ void stats_kernel(const float* __restrict__ x, int N,
                             float* __restrict__ statSum,
                             float* __restrict__ statSS) {
    __shared__ float sSum[128], sSS[128];
    if (threadIdx.x < 128) { sSum[threadIdx.x] = 0.f; sSS[threadIdx.x] = 0.f; }
    __syncthreads();
    float ls[4] = {0.f, 0.f, 0.f, 0.f}, lss[4] = {0.f, 0.f, 0.f, 0.f};
    size_t total = (size_t)N * 32;
    size_t stride = (size_t)gridDim.x * blockDim.x;
    const float4* x4 = (const float4*)x;
    for (size_t i = blockIdx.x * (size_t)blockDim.x + threadIdx.x; i < total; i += stride) {
        float4 v = x4[i];
        ls[0] += v.x; lss[0] += v.x * v.x;
        ls[1] += v.y; lss[1] += v.y * v.y;
        ls[2] += v.z; lss[2] += v.z * v.z;
        ls[3] += v.w; lss[3] += v.w * v.w;
    }
    int c4 = (threadIdx.x & 31) * 4;
#pragma unroll
    for (int q = 0; q < 4; q++) {
        atomicAdd(sSum + c4 + q, ls[q]);
        atomicAdd(sSS + c4 + q, lss[q]);
    }
    __syncthreads();
    if (threadIdx.x < 128) {
        atomicAdd(statSum + threadIdx.x, sSum[threadIdx.x]);
        atomicAdd(statSS + threadIdx.x, sSS[threadIdx.x]);
    }
}

__global__ void bn_final_kernel(float* __restrict__ x,
                                const float* __restrict__ stats, int statOff,
                                const float* __restrict__ g,
                                const float* __restrict__ beta, int N) {
    __shared__ float sScale[128], sShift[128];
    if (threadIdx.x < 128) {
        int j = threadIdx.x;
        float invN = 1.f / (float)N;
        float mu = stats[statOff + j] * invN;
        float var = fmaxf(stats[statOff + 128 + j] * invN - mu * mu, 0.f);
        float sc = g[j] * rsqrtf(var + 1e-5f);
        sScale[j] = sc;
        sShift[j] = beta[j] - mu * sc;
    }
    __syncthreads();
    size_t total = (size_t)N * 32;
    size_t i = blockIdx.x * (size_t)blockDim.x + threadIdx.x;
    size_t stride = (size_t)gridDim.x * blockDim.x;
    float4* x4 = (float4*)x;
    for (; i < total; i += stride) {
        int j = ((int)i & 31) * 4;
        float4 v = x4[i];
        v.x = v.x * sScale[j + 0] + sShift[j + 0];
        v.y = v.y * sScale[j + 1] + sShift[j + 1];
        v.z = v.z * sScale[j + 2] + sShift[j + 2];
        v.w = v.w * sScale[j + 3] + sShift[j + 3];
        x4[i] = v;
    }
}

// ---------------- launch -------------------------------------------------------
extern "C" void kernel_launch(void* const* d_in, const int* in_sizes, int n_in,
                              void* d_out, int out_size) {
    const float* x_student = (const float*)d_in[0];
    const float* x_item = (const float*)d_in[1];
    const int* responds_src = (const int*)d_in[2];
    const int* responds_dst = (const int*)d_in[3];
    const int* preceeds_src = (const int*)d_in[4];
    const int* preceeds_dst = (const int*)d_in[5];
    const float* sage_it_Wl = (const float*)d_in[6];
    const float* sage_it_Wr = (const float*)d_in[7];
    const float* sage_it_b = (const float*)d_in[8];
    const float* sage_st_Wl = (const float*)d_in[9];
    const float* sage_st_Wr = (const float*)d_in[10];
    const float* sage_st_b = (const float*)d_in[11];
    const float* sc_W1 = (const float*)d_in[12];
    const float* sc_b1 = (const float*)d_in[13];
    const float* sc_W2 = (const float*)d_in[14];
    const float* sc_b2 = (const float*)d_in[15];
    const float* bn_item_g = (const float*)d_in[16];
    const float* bn_item_b = (const float*)d_in[17];
    const float* bn_stu_g = (const float*)d_in[18];
    const float* bn_stu_b = (const float*)d_in[19];

    int n_stu = in_sizes[0] / D;
    int n_item = in_sizes[1] / D;
    int e_r = in_sizes[2];
    int e_p = in_sizes[4];

    const int DYN_SMEM = 2 * 128 * SA_STRIDE * 4;  // ~132 KB
    cudaFuncSetAttribute(gemm_rq_tc, cudaFuncAttributeMaxDynamicSharedMemorySize, DYN_SMEM);
    cudaFuncSetAttribute(out_item_tc, cudaFuncAttributeMaxDynamicSharedMemorySize, DYN_SMEM);
    cudaFuncSetAttribute(out_stu_tc, cudaFuncAttributeMaxDynamicSharedMemorySize, DYN_SMEM);

    void *pMeanI, *pMeanS, *pR, *pQ, *pH, *pStats;
    void *pRpItem, *pAdjItem, *pRpRs, *pAdjRs, *pRpP, *pAdjP;
    cudaGetSymbolAddress(&pMeanI, g_mean_item);
    cudaGetSymbolAddress(&pMeanS, g_mean_stu);
    cudaGetSymbolAddress(&pR, g_R);
    cudaGetSymbolAddress(&pQ, g_Q);
    cudaGetSymbolAddress(&pH, g_Hmean);
    cudaGetSymbolAddress(&pStats, g_stats);
    cudaGetSymbolAddress(&pRpItem, g_rp_item);
    cudaGetSymbolAddress(&pAdjItem, g_adj_item);
    cudaGetSymbolAddress(&pRpRs, g_rp_rs);
    cudaGetSymbolAddress(&pAdjRs, g_adj_rs);
    cudaGetSymbolAddress(&pRpP, g_rp_p);
    cudaGetSymbolAddress(&pAdjP, g_adj_p);

    float* out = (float*)d_out;
    float* out_item = out;
    float* out_stu = out + (size_t)n_item * D;

    int maxE = max(e_r, e_p);
    int gb_stu = (n_stu + 127) / 128;
    int gb_item = (n_item + 127) / 128;

    // CSR build
    zero_small_kernel<<<256, 256>>>();
    hist_kernel<<<(maxE + 255) / 256, 256>>>(responds_src, responds_dst, e_r,
                                             preceeds_dst, e_p);
    scan3_kernel<<<3, 1024>>>(n_item, n_stu);
    fill_kernel<<<(maxE + 255) / 256, 256>>>(responds_src, responds_dst, e_r,
                                             preceeds_src, preceeds_dst, e_p);

    // R/Q projections for SimpleConv
    gemm_rq_tc<<<gb_stu, 256, DYN_SMEM>>>(x_student, sc_W1, (float*)pR, (float*)pQ, n_stu);

    // CSR gather aggregations (means, no atomics)
    agg_csr_kernel<<<(n_item * 32 + 255) / 256, 256>>>(
        x_student, (const int*)pRpItem, (const int*)pAdjItem, (float*)pMeanI, n_item);
    agg_csr_kernel<<<(n_stu * 32 + 255) / 256, 256>>>(
        x_item, (const int*)pRpRs, (const int*)pAdjRs, (float*)pMeanS, n_stu);
    simple_csr_kernel<<<(n_stu * 32 + 255) / 256, 256>>>(
        (const float*)pR, (const float*)pQ, sc_b1, (const int*)pRpP,
        (const int*)pAdjP, (float*)pH, n_stu);

    // fused output GEMMs (elu written straight into d_out)
    out_item_tc<<<gb_item, 256, DYN_SMEM>>>((const float*)pMeanI, x_item, sage_it_Wl,
                                            sage_it_Wr, sage_it_b, out_item, n_item);
    out_stu_tc<<<gb_stu, 256, DYN_SMEM>>>((const float*)pMeanS, x_student,
                                          (const float*)pH, (const int*)pRpP,
                                          sage_st_Wl, sage_st_Wr, sc_W2, sage_st_b,
                                          sc_b2, out_stu, n_stu);

    // batch-norm: stats over d_out, then normalize in place
    float* stats = (float*)pStats;
    stats_kernel<<<512, 256>>>(out_item, n_item, stats + 0, stats + 128);
    stats_kernel<<<2048, 256>>>(out_stu, n_stu, stats + 256, stats + 384);
    bn_final_kernel<<<512, 256>>>(out_item, stats, 0, bn_item_g, bn_item_b, n_item);
    bn_final_kernel<<<2048, 256>>>(out_stu, stats, 256, bn_stu_g, bn_stu_b, n_stu);
}

// round 4
// speedup vs baseline: 1.2746x; 1.2746x over previous
#include <cuda_runtime.h>
#include <math.h>

#define D 128
#define MAX_N_STU 100000
#define MAX_N_ITEM 20000
#define SA_STRIDE 132   // 128 + 4 pad: conflict-free fragment LDS
#define TILE_M 64       // A-tile rows per block (smem 101KB -> 2 blocks/SM)

// ---------------- scratch (device globals; no allocation allowed) ------------
__device__ float g_agg_item[(size_t)MAX_N_ITEM * D];
__device__ float g_cnt_item[MAX_N_ITEM];
__device__ float g_agg_stu[(size_t)MAX_N_STU * D];
__device__ float g_cnt_stu[MAX_N_STU];
__device__ float g_R[(size_t)MAX_N_STU * D];
__device__ float g_Q[(size_t)MAX_N_STU * D];
__device__ float g_Hsum[(size_t)MAX_N_STU * D];
__device__ float g_cnt_p[MAX_N_STU];
__device__ float g_stats[4 * D];  // itemSum | itemSS | stuSum | stuSS

// ---------------- zero kernel -------------------------------------------------
__global__ void zero_all_kernel(int n_item, int n_stu) {
    size_t i = blockIdx.x * (size_t)blockDim.x + threadIdx.x;
    size_t stride = (size_t)gridDim.x * blockDim.x;
    size_t nS4 = (size_t)n_stu * 32, nI4 = (size_t)n_item * 32;
    float4 z = make_float4(0.f, 0.f, 0.f, 0.f);
    for (size_t x = i; x < nS4; x += stride) {
        ((float4*)g_agg_stu)[x] = z;
        ((float4*)g_Hsum)[x] = z;
        if (x < nI4) ((float4*)g_agg_item)[x] = z;
    }
    for (size_t x = i; x < (size_t)n_stu; x += stride) {
        g_cnt_stu[x] = 0.f;
        g_cnt_p[x] = 0.f;
        if (x < (size_t)n_item) g_cnt_item[x] = 0.f;
    }
    if (i < 4 * D) g_stats[i] = 0.f;
}

// ---------------- edge kernels (scatter, RED atomics) --------------------------
__device__ __forceinline__ void red_add_v4(float* p, float4 v) {
    asm volatile("red.global.add.v4.f32 [%0], {%1,%2,%3,%4};"
                 :: "l"(p), "f"(v.x), "f"(v.y), "f"(v.z), "f"(v.w) : "memory");
}

__global__ void edge_agg_kernel(const float* __restrict__ X,
                                const int* __restrict__ src,
                                const int* __restrict__ dst,
                                float* __restrict__ accum,
                                float* __restrict__ cnt, int E) {
    int w = (blockIdx.x * blockDim.x + threadIdx.x) >> 5;
    if (w >= E) return;
    int lane = threadIdx.x & 31;
    int s = src[w], d = dst[w];
    float4 v = ((const float4*)(X + (size_t)s * D))[lane];
    red_add_v4(accum + (size_t)d * D + lane * 4, v);
    if (lane == 0) atomicAdd(cnt + d, 1.0f);
}

__device__ __forceinline__ float elu1(float x) {
    return x > 0.f ? x : expm1f(x);
}

// Hsum[d] += elu(R[s] + Q[d] + b1)   (R = x@(W1top - W1bot), Q = x@W1bot)
__global__ void edge_simple_kernel(const float* __restrict__ R,
                                   const float* __restrict__ Q,
                                   const int* __restrict__ src,
                                   const int* __restrict__ dst,
                                   const float* __restrict__ b1,
                                   float* __restrict__ Hsum,
                                   float* __restrict__ cnt, int E) {
    int w = (blockIdx.x * blockDim.x + threadIdx.x) >> 5;
    if (w >= E) return;
    int lane = threadIdx.x & 31;
    int s = src[w], d = dst[w];
    float4 rs = ((const float4*)(R + (size_t)s * D))[lane];
    float4 qd = ((const float4*)(Q + (size_t)d * D))[lane];
    float4 bb = ((const float4*)b1)[lane];
    float4 h;
    h.x = elu1(rs.x + qd.x + bb.x);
    h.y = elu1(rs.y + qd.y + bb.y);
    h.z = elu1(rs.z + qd.z + bb.z);
    h.w = elu1(rs.w + qd.w + bb.w);
    red_add_v4(Hsum + (size_t)d * D + lane * 4, h);
    if (lane == 0) atomicAdd(cnt + d, 1.0f);
}

// ---------------- tensor-core GEMM pieces (tf32 mma.sync) ---------------------
__device__ __forceinline__ unsigned f2tf(float x) {
    unsigned r;
    asm("cvt.rna.tf32.f32 %0, %1;" : "=r"(r) : "f"(x));
    return r;
}

// Stage A tile: TILE_M rows x 128 K, optional mean-scale by cnt.
__device__ __forceinline__ void stage_A(const float* __restrict__ A,
                                        const float* __restrict__ cnt, int M,
                                        int rowBase, unsigned* sA) {
    for (int i = threadIdx.x; i < TILE_M * 32; i += 256) {
        int r = i >> 5, c4 = (i & 31) * 4;
        int gr = rowBase + r;
        float4 v = make_float4(0.f, 0.f, 0.f, 0.f);
        if (gr < M) {
            v = ((const float4*)(A + (size_t)gr * D))[c4 >> 2];
            if (cnt) {
                float inv = 1.f / fmaxf(cnt[gr], 1.f);
                v.x *= inv; v.y *= inv; v.z *= inv; v.w *= inv;
            }
        }
        uint4 u;
        u.x = f2tf(v.x); u.y = f2tf(v.y); u.z = f2tf(v.z); u.w = f2tf(v.w);
        *(uint4*)(sA + r * SA_STRIDE + c4) = u;
    }
}

// Stage W transposed: sW[n*SA_STRIDE + k] = tf32(W[k][n]).
__device__ __forceinline__ void stage_Wt(const float* __restrict__ W, unsigned* sW) {
    for (int i = threadIdx.x; i < 128 * 32; i += 256) {
        int k = i & 127, n4 = i >> 7;
        float4 v = ((const float4*)(W + (size_t)k * D))[n4];
        sW[(n4 * 4 + 0) * SA_STRIDE + k] = f2tf(v.x);
        sW[(n4 * 4 + 1) * SA_STRIDE + k] = f2tf(v.y);
        sW[(n4 * 4 + 2) * SA_STRIDE + k] = f2tf(v.z);
        sW[(n4 * 4 + 3) * SA_STRIDE + k] = f2tf(v.w);
    }
}

__device__ __forceinline__ void stage_Wt_diff(const float* __restrict__ Wa,
                                              const float* __restrict__ Wb,
                                              unsigned* sW) {
    for (int i = threadIdx.x; i < 128 * 32; i += 256) {
        int k = i & 127, n4 = i >> 7;
        float4 a = ((const float4*)(Wa + (size_t)k * D))[n4];
        float4 b = ((const float4*)(Wb + (size_t)k * D))[n4];
        sW[(n4 * 4 + 0) * SA_STRIDE + k] = f2tf(a.x - b.x);
        sW[(n4 * 4 + 1) * SA_STRIDE + k] = f2tf(a.y - b.y);
        sW[(n4 * 4 + 2) * SA_STRIDE + k] = f2tf(a.z - b.z);
        sW[(n4 * 4 + 3) * SA_STRIDE + k] = f2tf(a.w - b.w);
    }
}

// m32n32 warp tile: 8 warps = 2 row-groups x 4 col-groups over 64x128 block tile.
// acc[mi][j][0..3]: mi = m16 half, j = n8 tile within the 32-col group.
__device__ __forceinline__ void mm_tc32(const unsigned* sA, const unsigned* sW,
                                        float acc[2][4][4]) {
    int lane = threadIdx.x & 31, w = threadIdx.x >> 5;
    int g = lane >> 2, t = lane & 3;
    int rg = w >> 2, cg = w & 3;
    const unsigned* A0 = sA + (rg * 32 + g) * SA_STRIDE + t;
    const unsigned* B0 = sW + (cg * 32 + g) * SA_STRIDE + t;
#pragma unroll
    for (int k0 = 0; k0 < 128; k0 += 8) {
        unsigned a[2][4];
#pragma unroll
        for (int mi = 0; mi < 2; mi++) {
            const unsigned* Ab = A0 + mi * 16 * SA_STRIDE + k0;
            a[mi][0] = Ab[0];
            a[mi][1] = Ab[8 * SA_STRIDE];
            a[mi][2] = Ab[4];
            a[mi][3] = Ab[8 * SA_STRIDE + 4];
        }
#pragma unroll
        for (int j = 0; j < 4; j++) {
            const unsigned* Bb = B0 + j * 8 * SA_STRIDE + k0;
            unsigned b0 = Bb[0], b1 = Bb[4];
#pragma unroll
            for (int mi = 0; mi < 2; mi++) {
                asm volatile(
                    "mma.sync.aligned.m16n8k8.row.col.f32.tf32.tf32.f32 "
                    "{%0,%1,%2,%3},{%4,%5,%6,%7},{%8,%9},{%0,%1,%2,%3};"
                    : "+f"(acc[mi][j][0]), "+f"(acc[mi][j][1]),
                      "+f"(acc[mi][j][2]), "+f"(acc[mi][j][3])
                    : "r"(a[mi][0]), "r"(a[mi][1]), "r"(a[mi][2]), "r"(a[mi][3]),
                      "r"(b0), "r"(b1));
            }
        }
    }
}

// R = x@(W1top - W1bot), Q = x@W1bot; shares the staged A tile.
__global__ __launch_bounds__(256, 2) void gemm_rq_tc(const float* __restrict__ x,
                                                     const float* __restrict__ W1,
                                                     float* __restrict__ Rm,
                                                     float* __restrict__ Qm, int M) {
    extern __shared__ unsigned smem_u[];
    unsigned* sA = smem_u;
    unsigned* sW = smem_u + TILE_M * SA_STRIDE;
    int rowBase = blockIdx.x * TILE_M;
    int lane = threadIdx.x & 31, w = threadIdx.x >> 5;
    int g = lane >> 2, t = lane & 3;
    int rg = w >> 2, cg = w & 3;

    stage_A(x, nullptr, M, rowBase, sA);
    stage_Wt(W1 + 128 * D, sW);
    __syncthreads();
    {
        float acc[2][4][4] = {};
        mm_tc32(sA, sW, acc);
#pragma unroll
        for (int mi = 0; mi < 2; mi++) {
            int rA = rowBase + rg * 32 + mi * 16 + g, rB = rA + 8;
#pragma unroll
            for (int j = 0; j < 4; j++) {
                int c = cg * 32 + j * 8 + 2 * t;
                if (rA < M) *(float2*)(Qm + (size_t)rA * D + c) = make_float2(acc[mi][j][0], acc[mi][j][1]);
                if (rB < M) *(float2*)(Qm + (size_t)rB * D + c) = make_float2(acc[mi][j][2], acc[mi][j][3]);
            }
        }
    }
    __syncthreads();
    stage_Wt_diff(W1, W1 + 128 * D, sW);
    __syncthreads();
    {
        float acc[2][4][4] = {};
        mm_tc32(sA, sW, acc);
#pragma unroll
        for (int mi = 0; mi < 2; mi++) {
            int rA = rowBase + rg * 32 + mi * 16 + g, rB = rA + 8;
#pragma unroll
            for (int j = 0; j < 4; j++) {
                int c = cg * 32 + j * 8 + 2 * t;
                if (rA < M) *(float2*)(Rm + (size_t)rA * D + c) = make_float2(acc[mi][j][0], acc[mi][j][1]);
                if (rB < M) *(float2*)(Rm + (size_t)rB * D + c) = make_float2(acc[mi][j][2], acc[mi][j][3]);
            }
        }
    }
}

// Shared epilogue helper: smem + global reduction of per-column sums.
__device__ __forceinline__ void stats_reduce(float* sred, const float lsum[8],
                                             const float lss[8], int cg, int t,
                                             float* __restrict__ statSum,
                                             float* __restrict__ statSS) {
    __syncthreads();
    sred[threadIdx.x] = 0.f;  // 256 floats: [0:128) sum, [128:256) ss
    __syncthreads();
#pragma unroll
    for (int j = 0; j < 4; j++) {
        int c = cg * 32 + j * 8 + 2 * t;
        atomicAdd(&sred[c], lsum[2 * j]);
        atomicAdd(&sred[c + 1], lsum[2 * j + 1]);
        atomicAdd(&sred[128 + c], lss[2 * j]);
        atomicAdd(&sred[128 + c + 1], lss[2 * j + 1]);
    }
    __syncthreads();
    if (threadIdx.x < 128) {
        atomicAdd(statSum + threadIdx.x, sred[threadIdx.x]);
        atomicAdd(statSS + threadIdx.x, sred[128 + threadIdx.x]);
    }
}

// item pre-BN = elu( mean_agg@Wl + x_item@Wr + b ) -> out, + BN stats
__global__ __launch_bounds__(256, 2) void out_item_tc(
    const float* __restrict__ aggI, const float* __restrict__ cntI,
    const float* __restrict__ x_item, const float* __restrict__ Wl,
    const float* __restrict__ Wr, const float* __restrict__ b,
    float* __restrict__ out, float* __restrict__ stats, int M) {
    extern __shared__ unsigned smem_u[];
    unsigned* sA = smem_u;
    unsigned* sW = smem_u + TILE_M * SA_STRIDE;
    int rowBase = blockIdx.x * TILE_M;
    float acc[2][4][4] = {};

    stage_A(aggI, cntI, M, rowBase, sA);
    stage_Wt(Wl, sW);
    __syncthreads();
    mm_tc32(sA, sW, acc);
    __syncthreads();
    stage_A(x_item, nullptr, M, rowBase, sA);
    stage_Wt(Wr, sW);
    __syncthreads();
    mm_tc32(sA, sW, acc);

    int lane = threadIdx.x & 31, w = threadIdx.x >> 5;
    int g = lane >> 2, t = lane & 3;
    int rg = w >> 2, cg = w & 3;
    float lsum[8] = {}, lss[8] = {};
#pragma unroll
    for (int mi = 0; mi < 2; mi++) {
        int rA = rowBase + rg * 32 + mi * 16 + g, rB = rA + 8;
#pragma unroll
        for (int j = 0; j < 4; j++) {
            int c = cg * 32 + j * 8 + 2 * t;
            float b0v = b[c], b1v = b[c + 1];
            if (rA < M) {
                float e0 = elu1(acc[mi][j][0] + b0v);
                float e1 = elu1(acc[mi][j][1] + b1v);
                *(float2*)(out + (size_t)rA * D + c) = make_float2(e0, e1);
                lsum[2 * j] += e0; lss[2 * j] += e0 * e0;
                lsum[2 * j + 1] += e1; lss[2 * j + 1] += e1 * e1;
            }
            if (rB < M) {
                float e2 = elu1(acc[mi][j][2] + b0v);
                float e3 = elu1(acc[mi][j][3] + b1v);
                *(float2*)(out + (size_t)rB * D + c) = make_float2(e2, e3);
                lsum[2 * j] += e2; lss[2 * j] += e2 * e2;
                lsum[2 * j + 1] += e3; lss[2 * j + 1] += e3 * e3;
            }
        }
    }
    stats_reduce((float*)sA, lsum, lss, cg, t, stats + 0, stats + 128);
}

// stu pre-BN = elu( 0.5*( meanS@Wl + x@Wr + b_st + meanH@W2 + [cnt>0]*b2 ) )
__global__ __launch_bounds__(256, 2) void out_stu_tc(
    const float* __restrict__ aggS, const float* __restrict__ cntS,
    const float* __restrict__ x_stu, const float* __restrict__ Hsum,
    const float* __restrict__ cntP, const float* __restrict__ Wl,
    const float* __restrict__ Wr, const float* __restrict__ W2,
    const float* __restrict__ b_st, const float* __restrict__ b2,
    float* __restrict__ out, float* __restrict__ stats, int M) {
    extern __shared__ unsigned smem_u[];
    unsigned* sA = smem_u;
    unsigned* sW = smem_u + TILE_M * SA_STRIDE;
    int rowBase = blockIdx.x * TILE_M;
    float acc[2][4][4] = {};

    stage_A(aggS, cntS, M, rowBase, sA);
    stage_Wt(Wl, sW);
    __syncthreads();
    mm_tc32(sA, sW, acc);
    __syncthreads();
    stage_A(x_stu, nullptr, M, rowBase, sA);
    stage_Wt(Wr, sW);
    __syncthreads();
    mm_tc32(sA, sW, acc);
    __syncthreads();
    stage_A(Hsum, cntP, M, rowBase, sA);
    stage_Wt(W2, sW);
    __syncthreads();
    mm_tc32(sA, sW, acc);

    int lane = threadIdx.x & 31, w = threadIdx.x >> 5;
    int g = lane >> 2, t = lane & 3;
    int rg = w >> 2, cg = w & 3;
    float lsum[8] = {}, lss[8] = {};
#pragma unroll
    for (int mi = 0; mi < 2; mi++) {
        int rA = rowBase + rg * 32 + mi * 16 + g, rB = rA + 8;
        float hA = (rA < M && cntP[rA] > 0.f) ? 1.f : 0.f;
        float hB = (rB < M && cntP[rB] > 0.f) ? 1.f : 0.f;
#pragma unroll
        for (int j = 0; j < 4; j++) {
            int c = cg * 32 + j * 8 + 2 * t;
            float bs0 = b_st[c], bs1 = b_st[c + 1];
            float b20 = b2[c], b21 = b2[c + 1];
            if (rA < M) {
                float e0 = elu1(0.5f * (acc[mi][j][0] + bs0 + hA * b20));
                float e1 = elu1(0.5f * (acc[mi][j][1] + bs1 + hA * b21));
                *(float2*)(out + (size_t)rA * D + c) = make_float2(e0, e1);
                lsum[2 * j] += e0; lss[2 * j] += e0 * e0;
                lsum[2 * j + 1] += e1; lss[2 * j + 1] += e1 * e1;
            }
            if (rB < M) {
                float e2 = elu1(0.5f * (acc[mi][j][2] + bs0 + hB * b20));
                float e3 = elu1(0.5f * (acc[mi][j][3] + bs1 + hB * b21));
                *(float2*)(out + (size_t)rB * D + c) = make_float2(e2, e3);
                lsum[2 * j] += e2; lss[2 * j] += e2 * e2;
                lsum[2 * j + 1] += e3; lss[2 * j + 1] += e3 * e3;
            }
        }
    }
    stats_reduce((float*)sA, lsum, lss, cg, t, stats + 256, stats + 384);
}

// ---------------- batch-norm finalize -----------------------------------------
__global__ void bn_final_kernel(float* __restrict__ x,
                                const float* __restrict__ stats, int statOff,
                                const float* __restrict__ g,
                                const float* __restrict__ beta, int N) {
    __shared__ float sScale[128], sShift[128];
    if (threadIdx.x < 128) {
        int j = threadIdx.x;
        float invN = 1.f / (float)N;
        float mu = stats[statOff + j] * invN;
        float var = fmaxf(stats[statOff + 128 + j] * invN - mu * mu, 0.f);
        float sc = g[j] * rsqrtf(var + 1e-5f);
        sScale[j] = sc;
        sShift[j] = beta[j] - mu * sc;
    }
    __syncthreads();
    size_t total = (size_t)N * 32;
    size_t i = blockIdx.x * (size_t)blockDim.x + threadIdx.x;
    size_t stride = (size_t)gridDim.x * blockDim.x;
    float4* x4 = (float4*)x;
    for (; i < total; i += stride) {
        int j = ((int)i & 31) * 4;
        float4 v = x4[i];
        v.x = v.x * sScale[j + 0] + sShift[j + 0];
        v.y = v.y * sScale[j + 1] + sShift[j + 1];
        v.z = v.z * sScale[j + 2] + sShift[j + 2];
        v.w = v.w * sScale[j + 3] + sShift[j + 3];
        x4[i] = v;
    }
}

// ---------------- launch -------------------------------------------------------
extern "C" void kernel_launch(void* const* d_in, const int* in_sizes, int n_in,
                              void* d_out, int out_size) {
    const float* x_student = (const float*)d_in[0];
    const float* x_item = (const float*)d_in[1];
    const int* responds_src = (const int*)d_in[2];
    const int* responds_dst = (const int*)d_in[3];
    const int* preceeds_src = (const int*)d_in[4];
    const int* preceeds_dst = (const int*)d_in[5];
    const float* sage_it_Wl = (const float*)d_in[6];
    const float* sage_it_Wr = (const float*)d_in[7];
    const float* sage_it_b = (const float*)d_in[8];
    const float* sage_st_Wl = (const float*)d_in[9];
    const float* sage_st_Wr = (const float*)d_in[10];
    const float* sage_st_b = (const float*)d_in[11];
    const float* sc_W1 = (const float*)d_in[12];
    const float* sc_b1 = (const float*)d_in[13];
    const float* sc_W2 = (const float*)d_in[14];
    const float* sc_b2 = (const float*)d_in[15];
    const float* bn_item_g = (const float*)d_in[16];
    const float* bn_item_b = (const float*)d_in[17];
    const float* bn_stu_g = (const float*)d_in[18];
    const float* bn_stu_b = (const float*)d_in[19];

    int n_stu = in_sizes[0] / D;
    int n_item = in_sizes[1] / D;
    int e_r = in_sizes[2];
    int e_p = in_sizes[4];

    const int DYN_SMEM = (TILE_M + 128) * SA_STRIDE * 4;  // 101376 B
    cudaFuncSetAttribute(gemm_rq_tc, cudaFuncAttributeMaxDynamicSharedMemorySize, DYN_SMEM);
    cudaFuncSetAttribute(out_item_tc, cudaFuncAttributeMaxDynamicSharedMemorySize, DYN_SMEM);
    cudaFuncSetAttribute(out_stu_tc, cudaFuncAttributeMaxDynamicSharedMemorySize, DYN_SMEM);

    void *pAggI, *pCntI, *pAggS, *pCntS, *pR, *pQ, *pH, *pCntP, *pStats;
    cudaGetSymbolAddress(&pAggI, g_agg_item);
    cudaGetSymbolAddress(&pCntI, g_cnt_item);
    cudaGetSymbolAddress(&pAggS, g_agg_stu);
    cudaGetSymbolAddress(&pCntS, g_cnt_stu);
    cudaGetSymbolAddress(&pR, g_R);
    cudaGetSymbolAddress(&pQ, g_Q);
    cudaGetSymbolAddress(&pH, g_Hsum);
    cudaGetSymbolAddress(&pCntP, g_cnt_p);
    cudaGetSymbolAddress(&pStats, g_stats);

    float* out = (float*)d_out;
    float* out_item = out;
    float* out_stu = out + (size_t)n_item * D;

    int gb_stu = (n_stu + TILE_M - 1) / TILE_M;
    int gb_item = (n_item + TILE_M - 1) / TILE_M;

    zero_all_kernel<<<2048, 256>>>(n_item, n_stu);

    // R/Q projections for SimpleConv (share the staged A tile)
    gemm_rq_tc<<<gb_stu, 256, DYN_SMEM>>>(x_student, sc_W1, (float*)pR, (float*)pQ, n_stu);

    // edge scatter aggregations
    edge_agg_kernel<<<(e_r + 7) / 8, 256>>>(x_student, responds_src, responds_dst,
                                            (float*)pAggI, (float*)pCntI, e_r);
    edge_agg_kernel<<<(e_r + 7) / 8, 256>>>(x_item, responds_dst, responds_src,
                                            (float*)pAggS, (float*)pCntS, e_r);
    edge_simple_kernel<<<(e_p + 7) / 8, 256>>>((const float*)pR, (const float*)pQ,
                                               preceeds_src, preceeds_dst, sc_b1,
                                               (float*)pH, (float*)pCntP, e_p);

    // fused output GEMMs (elu -> d_out, BN stats in epilogue)
    float* stats = (float*)pStats;
    out_item_tc<<<gb_item, 256, DYN_SMEM>>>((const float*)pAggI, (const float*)pCntI,
                                            x_item, sage_it_Wl, sage_it_Wr, sage_it_b,
                                            out_item, stats, n_item);
    out_stu_tc<<<gb_stu, 256, DYN_SMEM>>>((const float*)pAggS, (const float*)pCntS,
                                          x_student, (const float*)pH, (const float*)pCntP,
                                          sage_st_Wl, sage_st_Wr, sc_W2, sage_st_b, sc_b2,
                                          out_stu, stats, n_stu);

    // batch-norm normalize in place
    bn_final_kernel<<<512, 256>>>(out_item, stats, 0, bn_item_g, bn_item_b, n_item);
    bn_final_kernel<<<2048, 256>>>(out_stu, stats, 256, bn_stu_g, bn_stu_b, n_stu);
}

// round 5
// speedup vs baseline: 1.4265x; 1.1191x over previous
#include <cuda_runtime.h>
#include <math.h>

#define D 128
#define MAX_N_STU 100000
#define MAX_N_ITEM 20000
#define SA_STRIDE 132   // 128 + 4 pad: conflict-free fragment LDS
#define TILE_M 64       // A-tile rows per block (smem 101KB -> 2 blocks/SM)

// ---------------- scratch (device globals; no allocation allowed) ------------
__device__ float g_agg_item[(size_t)MAX_N_ITEM * D];
__device__ float g_cnt_item[MAX_N_ITEM];
__device__ float g_aggY_stu[(size_t)MAX_N_STU * D];   // sum of Y over rev edges
__device__ float g_cnt_stu[MAX_N_STU];
__device__ float g_Y[(size_t)MAX_N_ITEM * D];          // x_item @ sage_st_Wl
__device__ float g_R[(size_t)MAX_N_STU * D];
__device__ float g_Q[(size_t)MAX_N_STU * D];
__device__ float g_Hsum[(size_t)MAX_N_STU * D];
__device__ float g_cnt_p[MAX_N_STU];
__device__ float g_stats[4 * D];  // itemSum | itemSS | stuSum | stuSS

// ---------------- zero kernel -------------------------------------------------
__global__ void zero_all_kernel(int n_item, int n_stu) {
    size_t i = blockIdx.x * (size_t)blockDim.x + threadIdx.x;
    size_t stride = (size_t)gridDim.x * blockDim.x;
    size_t nS4 = (size_t)n_stu * 32, nI4 = (size_t)n_item * 32;
    float4 z = make_float4(0.f, 0.f, 0.f, 0.f);
    for (size_t x = i; x < nS4; x += stride) {
        ((float4*)g_aggY_stu)[x] = z;
        ((float4*)g_Hsum)[x] = z;
        if (x < nI4) ((float4*)g_agg_item)[x] = z;
    }
    for (size_t x = i; x < (size_t)n_stu; x += stride) {
        g_cnt_stu[x] = 0.f;
        g_cnt_p[x] = 0.f;
        if (x < (size_t)n_item) g_cnt_item[x] = 0.f;
    }
    if (i < 4 * D) g_stats[i] = 0.f;
}

// ---------------- edge kernels (scatter, RED atomics) --------------------------
__device__ __forceinline__ void red_add_v4(float* p, float4 v) {
    asm volatile("red.global.add.v4.f32 [%0], {%1,%2,%3,%4};"
                 :: "l"(p), "f"(v.x), "f"(v.y), "f"(v.z), "f"(v.w) : "memory");
}

__global__ void edge_agg_kernel(const float* __restrict__ X,
                                const int* __restrict__ src,
                                const int* __restrict__ dst,
                                float* __restrict__ accum,
                                float* __restrict__ cnt, int E) {
    int w = (blockIdx.x * blockDim.x + threadIdx.x) >> 5;
    if (w >= E) return;
    int lane = threadIdx.x & 31;
    int s = src[w], d = dst[w];
    float4 v = ((const float4*)(X + (size_t)s * D))[lane];
    red_add_v4(accum + (size_t)d * D + lane * 4, v);
    if (lane == 0) atomicAdd(cnt + d, 1.0f);
}

__device__ __forceinline__ float elu1(float x) {
    return x > 0.f ? x : expm1f(x);
}

// Hsum[d] += elu(R[s] + Q[d] + b1)   (R = x@(W1top - W1bot), Q = x@W1bot)
__global__ void edge_simple_kernel(const float* __restrict__ R,
                                   const float* __restrict__ Q,
                                   const int* __restrict__ src,
                                   const int* __restrict__ dst,
                                   const float* __restrict__ b1,
                                   float* __restrict__ Hsum,
                                   float* __restrict__ cnt, int E) {
    int w = (blockIdx.x * blockDim.x + threadIdx.x) >> 5;
    if (w >= E) return;
    int lane = threadIdx.x & 31;
    int s = src[w], d = dst[w];
    float4 rs = ((const float4*)(R + (size_t)s * D))[lane];
    float4 qd = ((const float4*)(Q + (size_t)d * D))[lane];
    float4 bb = ((const float4*)b1)[lane];
    float4 h;
    h.x = elu1(rs.x + qd.x + bb.x);
    h.y = elu1(rs.y + qd.y + bb.y);
    h.z = elu1(rs.z + qd.z + bb.z);
    h.w = elu1(rs.w + qd.w + bb.w);
    red_add_v4(Hsum + (size_t)d * D + lane * 4, h);
    if (lane == 0) atomicAdd(cnt + d, 1.0f);
}

// ---------------- tensor-core GEMM pieces (tf32 mma.sync) ---------------------
__device__ __forceinline__ unsigned f2tf(float x) {
    unsigned r;
    asm("cvt.rna.tf32.f32 %0, %1;" : "=r"(r) : "f"(x));
    return r;
}

__device__ __forceinline__ void stage_A(const float* __restrict__ A,
                                        const float* __restrict__ cnt, int M,
                                        int rowBase, unsigned* sA) {
    for (int i = threadIdx.x; i < TILE_M * 32; i += 256) {
        int r = i >> 5, c4 = (i & 31) * 4;
        int gr = rowBase + r;
        float4 v = make_float4(0.f, 0.f, 0.f, 0.f);
        if (gr < M) {
            v = ((const float4*)(A + (size_t)gr * D))[c4 >> 2];
            if (cnt) {
                float inv = 1.f / fmaxf(cnt[gr], 1.f);
                v.x *= inv; v.y *= inv; v.z *= inv; v.w *= inv;
            }
        }
        uint4 u;
        u.x = f2tf(v.x); u.y = f2tf(v.y); u.z = f2tf(v.z); u.w = f2tf(v.w);
        *(uint4*)(sA + r * SA_STRIDE + c4) = u;
    }
}

__device__ __forceinline__ void stage_Wt(const float* __restrict__ W, unsigned* sW) {
    for (int i = threadIdx.x; i < 128 * 32; i += 256) {
        int k = i & 127, n4 = i >> 7;
        float4 v = ((const float4*)(W + (size_t)k * D))[n4];
        sW[(n4 * 4 + 0) * SA_STRIDE + k] = f2tf(v.x);
        sW[(n4 * 4 + 1) * SA_STRIDE + k] = f2tf(v.y);
        sW[(n4 * 4 + 2) * SA_STRIDE + k] = f2tf(v.z);
        sW[(n4 * 4 + 3) * SA_STRIDE + k] = f2tf(v.w);
    }
}

__device__ __forceinline__ void stage_Wt_diff(const float* __restrict__ Wa,
                                              const float* __restrict__ Wb,
                                              unsigned* sW) {
    for (int i = threadIdx.x; i < 128 * 32; i += 256) {
        int k = i & 127, n4 = i >> 7;
        float4 a = ((const float4*)(Wa + (size_t)k * D))[n4];
        float4 b = ((const float4*)(Wb + (size_t)k * D))[n4];
        sW[(n4 * 4 + 0) * SA_STRIDE + k] = f2tf(a.x - b.x);
        sW[(n4 * 4 + 1) * SA_STRIDE + k] = f2tf(a.y - b.y);
        sW[(n4 * 4 + 2) * SA_STRIDE + k] = f2tf(a.z - b.z);
        sW[(n4 * 4 + 3) * SA_STRIDE + k] = f2tf(a.w - b.w);
    }
}

// m32n32 warp tile over 64x128 block tile.
__device__ __forceinline__ void mm_tc32(const unsigned* sA, const unsigned* sW,
                                        float acc[2][4][4]) {
    int lane = threadIdx.x & 31, w = threadIdx.x >> 5;
    int g = lane >> 2, t = lane & 3;
    int rg = w >> 2, cg = w & 3;
    const unsigned* A0 = sA + (rg * 32 + g) * SA_STRIDE + t;
    const unsigned* B0 = sW + (cg * 32 + g) * SA_STRIDE + t;
#pragma unroll
    for (int k0 = 0; k0 < 128; k0 += 8) {
        unsigned a[2][4];
#pragma unroll
        for (int mi = 0; mi < 2; mi++) {
            const unsigned* Ab = A0 + mi * 16 * SA_STRIDE + k0;
            a[mi][0] = Ab[0];
            a[mi][1] = Ab[8 * SA_STRIDE];
            a[mi][2] = Ab[4];
            a[mi][3] = Ab[8 * SA_STRIDE + 4];
        }
#pragma unroll
        for (int j = 0; j < 4; j++) {
            const unsigned* Bb = B0 + j * 8 * SA_STRIDE + k0;
            unsigned b0 = Bb[0], b1 = Bb[4];
#pragma unroll
            for (int mi = 0; mi < 2; mi++) {
                asm volatile(
                    "mma.sync.aligned.m16n8k8.row.col.f32.tf32.tf32.f32 "
                    "{%0,%1,%2,%3},{%4,%5,%6,%7},{%8,%9},{%0,%1,%2,%3};"
                    : "+f"(acc[mi][j][0]), "+f"(acc[mi][j][1]),
                      "+f"(acc[mi][j][2]), "+f"(acc[mi][j][3])
                    : "r"(a[mi][0]), "r"(a[mi][1]), "r"(a[mi][2]), "r"(a[mi][3]),
                      "r"(b0), "r"(b1));
            }
        }
    }
}

__device__ __forceinline__ void store_tile(float* __restrict__ C, int M, int rowBase,
                                           float acc[2][4][4]) {
    int lane = threadIdx.x & 31, w = threadIdx.x >> 5;
    int g = lane >> 2, t = lane & 3;
    int rg = w >> 2, cg = w & 3;
#pragma unroll
    for (int mi = 0; mi < 2; mi++) {
        int rA = rowBase + rg * 32 + mi * 16 + g, rB = rA + 8;
#pragma unroll
        for (int j = 0; j < 4; j++) {
            int c = cg * 32 + j * 8 + 2 * t;
            if (rA < M) *(float2*)(C + (size_t)rA * D + c) = make_float2(acc[mi][j][0], acc[mi][j][1]);
            if (rB < M) *(float2*)(C + (size_t)rB * D + c) = make_float2(acc[mi][j][2], acc[mi][j][3]);
        }
    }
}

// C = A @ W  (single mm)
__global__ __launch_bounds__(256, 2) void gemm_one_tc(const float* __restrict__ A,
                                                      const float* __restrict__ W,
                                                      float* __restrict__ C, int M) {
    extern __shared__ unsigned smem_u[];
    unsigned* sA = smem_u;
    unsigned* sW = smem_u + TILE_M * SA_STRIDE;
    int rowBase = blockIdx.x * TILE_M;
    float acc[2][4][4] = {};
    stage_A(A, nullptr, M, rowBase, sA);
    stage_Wt(W, sW);
    __syncthreads();
    mm_tc32(sA, sW, acc);
    store_tile(C, M, rowBase, acc);
}

// R = x@(W1top - W1bot), Q = x@W1bot; shares the staged A tile.
__global__ __launch_bounds__(256, 2) void gemm_rq_tc(const float* __restrict__ x,
                                                     const float* __restrict__ W1,
                                                     float* __restrict__ Rm,
                                                     float* __restrict__ Qm, int M) {
    extern __shared__ unsigned smem_u[];
    unsigned* sA = smem_u;
    unsigned* sW = smem_u + TILE_M * SA_STRIDE;
    int rowBase = blockIdx.x * TILE_M;

    stage_A(x, nullptr, M, rowBase, sA);
    stage_Wt(W1 + 128 * D, sW);
    __syncthreads();
    {
        float acc[2][4][4] = {};
        mm_tc32(sA, sW, acc);
        store_tile(Qm, M, rowBase, acc);
    }
    __syncthreads();
    stage_Wt_diff(W1, W1 + 128 * D, sW);
    __syncthreads();
    {
        float acc[2][4][4] = {};
        mm_tc32(sA, sW, acc);
        store_tile(Rm, M, rowBase, acc);
    }
}

// Shared epilogue helper: smem + global reduction of per-column sums.
__device__ __forceinline__ void stats_reduce(float* sred, const float lsum[8],
                                             const float lss[8], int cg, int t,
                                             float* __restrict__ statSum,
                                             float* __restrict__ statSS) {
    __syncthreads();
    sred[threadIdx.x] = 0.f;
    __syncthreads();
#pragma unroll
    for (int j = 0; j < 4; j++) {
        int c = cg * 32 + j * 8 + 2 * t;
        atomicAdd(&sred[c], lsum[2 * j]);
        atomicAdd(&sred[c + 1], lsum[2 * j + 1]);
        atomicAdd(&sred[128 + c], lss[2 * j]);
        atomicAdd(&sred[128 + c + 1], lss[2 * j + 1]);
    }
    __syncthreads();
    if (threadIdx.x < 128) {
        atomicAdd(statSum + threadIdx.x, sred[threadIdx.x]);
        atomicAdd(statSS + threadIdx.x, sred[128 + threadIdx.x]);
    }
}

// item pre-BN = elu( mean_agg@Wl + x_item@Wr + b ) -> out, + BN stats
__global__ __launch_bounds__(256, 2) void out_item_tc(
    const float* __restrict__ aggI, const float* __restrict__ cntI,
    const float* __restrict__ x_item, const float* __restrict__ Wl,
    const float* __restrict__ Wr, const float* __restrict__ b,
    float* __restrict__ out, float* __restrict__ stats, int M) {
    extern __shared__ unsigned smem_u[];
    unsigned* sA = smem_u;
    unsigned* sW = smem_u + TILE_M * SA_STRIDE;
    int rowBase = blockIdx.x * TILE_M;
    float acc[2][4][4] = {};

    stage_A(aggI, cntI, M, rowBase, sA);
    stage_Wt(Wl, sW);
    __syncthreads();
    mm_tc32(sA, sW, acc);
    __syncthreads();
    stage_A(x_item, nullptr, M, rowBase, sA);
    stage_Wt(Wr, sW);
    __syncthreads();
    mm_tc32(sA, sW, acc);

    int lane = threadIdx.x & 31, w = threadIdx.x >> 5;
    int g = lane >> 2, t = lane & 3;
    int rg = w >> 2, cg = w & 3;
    float lsum[8] = {}, lss[8] = {};
#pragma unroll
    for (int mi = 0; mi < 2; mi++) {
        int rA = rowBase + rg * 32 + mi * 16 + g, rB = rA + 8;
#pragma unroll
        for (int j = 0; j < 4; j++) {
            int c = cg * 32 + j * 8 + 2 * t;
            float b0v = b[c], b1v = b[c + 1];
            if (rA < M) {
                float e0 = elu1(acc[mi][j][0] + b0v);
                float e1 = elu1(acc[mi][j][1] + b1v);
                *(float2*)(out + (size_t)rA * D + c) = make_float2(e0, e1);
                lsum[2 * j] += e0; lss[2 * j] += e0 * e0;
                lsum[2 * j + 1] += e1; lss[2 * j + 1] += e1 * e1;
            }
            if (rB < M) {
                float e2 = elu1(acc[mi][j][2] + b0v);
                float e3 = elu1(acc[mi][j][3] + b1v);
                *(float2*)(out + (size_t)rB * D + c) = make_float2(e2, e3);
                lsum[2 * j] += e2; lss[2 * j] += e2 * e2;
                lsum[2 * j + 1] += e3; lss[2 * j + 1] += e3 * e3;
            }
        }
    }
    stats_reduce((float*)sA, lsum, lss, cg, t, stats + 0, stats + 128);
}

// stu pre-BN = elu( 0.5*( meanY + x@Wr + b_st + meanH@W2 + [cnt>0]*b2 ) )
// meanY = aggY/cnt added in epilogue (projection commuted with the mean).
__global__ __launch_bounds__(256, 2) void out_stu_tc(
    const float* __restrict__ aggY, const float* __restrict__ cntS,
    const float* __restrict__ x_stu, const float* __restrict__ Hsum,
    const float* __restrict__ cntP, const float* __restrict__ Wr,
    const float* __restrict__ W2, const float* __restrict__ b_st,
    const float* __restrict__ b2, float* __restrict__ out,
    float* __restrict__ stats, int M) {
    extern __shared__ unsigned smem_u[];
    unsigned* sA = smem_u;
    unsigned* sW = smem_u + TILE_M * SA_STRIDE;
    int rowBase = blockIdx.x * TILE_M;
    float acc[2][4][4] = {};

    stage_A(x_stu, nullptr, M, rowBase, sA);
    stage_Wt(Wr, sW);
    __syncthreads();
    mm_tc32(sA, sW, acc);
    __syncthreads();
    stage_A(Hsum, cntP, M, rowBase, sA);
    stage_Wt(W2, sW);
    __syncthreads();
    mm_tc32(sA, sW, acc);

    int lane = threadIdx.x & 31, w = threadIdx.x >> 5;
    int g = lane >> 2, t = lane & 3;
    int rg = w >> 2, cg = w & 3;
    float lsum[8] = {}, lss[8] = {};
#pragma unroll
    for (int mi = 0; mi < 2; mi++) {
        int rA = rowBase + rg * 32 + mi * 16 + g, rB = rA + 8;
        float hA = 0.f, invA = 0.f, hB = 0.f, invB = 0.f;
        if (rA < M) {
            hA = (cntP[rA] > 0.f) ? 1.f : 0.f;
            invA = 1.f / fmaxf(cntS[rA], 1.f);
        }
        if (rB < M) {
            hB = (cntP[rB] > 0.f) ? 1.f : 0.f;
            invB = 1.f / fmaxf(cntS[rB], 1.f);
        }
#pragma unroll
        for (int j = 0; j < 4; j++) {
            int c = cg * 32 + j * 8 + 2 * t;
            float bs0 = b_st[c], bs1 = b_st[c + 1];
            float b20 = b2[c], b21 = b2[c + 1];
            if (rA < M) {
                float2 y = *(const float2*)(aggY + (size_t)rA * D + c);
                float e0 = elu1(0.5f * (acc[mi][j][0] + y.x * invA + bs0 + hA * b20));
                float e1 = elu1(0.5f * (acc[mi][j][1] + y.y * invA + bs1 + hA * b21));
                *(float2*)(out + (size_t)rA * D + c) = make_float2(e0, e1);
                lsum[2 * j] += e0; lss[2 * j] += e0 * e0;
                lsum[2 * j + 1] += e1; lss[2 * j + 1] += e1 * e1;
            }
            if (rB < M) {
                float2 y = *(const float2*)(aggY + (size_t)rB * D + c);
                float e2 = elu1(0.5f * (acc[mi][j][2] + y.x * invB + bs0 + hB * b20));
                float e3 = elu1(0.5f * (acc[mi][j][3] + y.y * invB + bs1 + hB * b21));
                *(float2*)(out + (size_t)rB * D + c) = make_float2(e2, e3);
                lsum[2 * j] += e2; lss[2 * j] += e2 * e2;
                lsum[2 * j + 1] += e3; lss[2 * j + 1] += e3 * e3;
            }
        }
    }
    stats_reduce((float*)sA, lsum, lss, cg, t, stats + 256, stats + 384);
}

// ---------------- batch-norm finalize -----------------------------------------
__global__ void bn_final_kernel(float* __restrict__ x,
                                const float* __restrict__ stats, int statOff,
                                const float* __restrict__ g,
                                const float* __restrict__ beta, int N) {
    __shared__ float sScale[128], sShift[128];
    if (threadIdx.x < 128) {
        int j = threadIdx.x;
        float invN = 1.f / (float)N;
        float mu = stats[statOff + j] * invN;
        float var = fmaxf(stats[statOff + 128 + j] * invN - mu * mu, 0.f);
        float sc = g[j] * rsqrtf(var + 1e-5f);
        sScale[j] = sc;
        sShift[j] = beta[j] - mu * sc;
    }
    __syncthreads();
    size_t total = (size_t)N * 32;
    size_t i = blockIdx.x * (size_t)blockDim.x + threadIdx.x;
    size_t stride = (size_t)gridDim.x * blockDim.x;
    float4* x4 = (float4*)x;
    for (; i < total; i += stride) {
        int j = ((int)i & 31) * 4;
        float4 v = x4[i];
        v.x = v.x * sScale[j + 0] + sShift[j + 0];
        v.y = v.y * sScale[j + 1] + sShift[j + 1];
        v.z = v.z * sScale[j + 2] + sShift[j + 2];
        v.w = v.w * sScale[j + 3] + sShift[j + 3];
        x4[i] = v;
    }
}

// ---------------- launch -------------------------------------------------------
extern "C" void kernel_launch(void* const* d_in, const int* in_sizes, int n_in,
                              void* d_out, int out_size) {
    const float* x_student = (const float*)d_in[0];
    const float* x_item = (const float*)d_in[1];
    const int* responds_src = (const int*)d_in[2];
    const int* responds_dst = (const int*)d_in[3];
    const int* preceeds_src = (const int*)d_in[4];
    const int* preceeds_dst = (const int*)d_in[5];
    const float* sage_it_Wl = (const float*)d_in[6];
    const float* sage_it_Wr = (const float*)d_in[7];
    const float* sage_it_b = (const float*)d_in[8];
    const float* sage_st_Wl = (const float*)d_in[9];
    const float* sage_st_Wr = (const float*)d_in[10];
    const float* sage_st_b = (const float*)d_in[11];
    const float* sc_W1 = (const float*)d_in[12];
    const float* sc_b1 = (const float*)d_in[13];
    const float* sc_W2 = (const float*)d_in[14];
    const float* sc_b2 = (const float*)d_in[15];
    const float* bn_item_g = (const float*)d_in[16];
    const float* bn_item_b = (const float*)d_in[17];
    const float* bn_stu_g = (const float*)d_in[18];
    const float* bn_stu_b = (const float*)d_in[19];

    int n_stu = in_sizes[0] / D;
    int n_item = in_sizes[1] / D;
    int e_r = in_sizes[2];
    int e_p = in_sizes[4];

    const int DYN_SMEM = (TILE_M + 128) * SA_STRIDE * 4;  // 101376 B

    // One-time host-side resources (no device memory involved).
    static cudaStream_t s1 = nullptr;
    static cudaEvent_t eStart, eY, eG, eA1, eJoin;
    if (s1 == nullptr) {
        cudaStreamCreateWithFlags(&s1, cudaStreamNonBlocking);
        cudaEventCreateWithFlags(&eStart, cudaEventDisableTiming);
        cudaEventCreateWithFlags(&eY, cudaEventDisableTiming);
        cudaEventCreateWithFlags(&eG, cudaEventDisableTiming);
        cudaEventCreateWithFlags(&eA1, cudaEventDisableTiming);
        cudaEventCreateWithFlags(&eJoin, cudaEventDisableTiming);
        cudaFuncSetAttribute(gemm_one_tc, cudaFuncAttributeMaxDynamicSharedMemorySize, DYN_SMEM);
        cudaFuncSetAttribute(gemm_rq_tc, cudaFuncAttributeMaxDynamicSharedMemorySize, DYN_SMEM);
        cudaFuncSetAttribute(out_item_tc, cudaFuncAttributeMaxDynamicSharedMemorySize, DYN_SMEM);
        cudaFuncSetAttribute(out_stu_tc, cudaFuncAttributeMaxDynamicSharedMemorySize, DYN_SMEM);
    }

    void *pAggI, *pCntI, *pAggY, *pCntS, *pY, *pR, *pQ, *pH, *pCntP, *pStats;
    cudaGetSymbolAddress(&pAggI, g_agg_item);
    cudaGetSymbolAddress(&pCntI, g_cnt_item);
    cudaGetSymbolAddress(&pAggY, g_aggY_stu);
    cudaGetSymbolAddress(&pCntS, g_cnt_stu);
    cudaGetSymbolAddress(&pY, g_Y);
    cudaGetSymbolAddress(&pR, g_R);
    cudaGetSymbolAddress(&pQ, g_Q);
    cudaGetSymbolAddress(&pH, g_Hsum);
    cudaGetSymbolAddress(&pCntP, g_cnt_p);
    cudaGetSymbolAddress(&pStats, g_stats);

    float* out = (float*)d_out;
    float* out_item = out;
    float* out_stu = out + (size_t)n_item * D;
    float* stats = (float*)pStats;

    int gb_stu = (n_stu + TILE_M - 1) / TILE_M;
    int gb_item = (n_item + TILE_M - 1) / TILE_M;

    // ---- fork: s1 runs the projection GEMMs while s0 zeroes + aggregates ----
    cudaEventRecord(eStart, 0);
    cudaStreamWaitEvent(s1, eStart, 0);

    // s1: Y = x_item @ sage_st_Wl   (projection commuted with the mean)
    gemm_one_tc<<<gb_item, 256, DYN_SMEM, s1>>>(x_item, sage_st_Wl, (float*)pY, n_item);
    cudaEventRecord(eY, s1);
    // s1: R/Q projections for SimpleConv
    gemm_rq_tc<<<gb_stu, 256, DYN_SMEM, s1>>>(x_student, sc_W1, (float*)pR, (float*)pQ, n_stu);
    cudaEventRecord(eG, s1);

    // s0: zero + responds->item aggregation (independent of the GEMMs)
    zero_all_kernel<<<2048, 256>>>(n_item, n_stu);
    edge_agg_kernel<<<(e_r + 7) / 8, 256>>>(x_student, responds_src, responds_dst,
                                            (float*)pAggI, (float*)pCntI, e_r);
    cudaEventRecord(eA1, 0);

    // s1: item output path (needs aggI + zeroed stats)
    cudaStreamWaitEvent(s1, eA1, 0);
    out_item_tc<<<gb_item, 256, DYN_SMEM, s1>>>((const float*)pAggI, (const float*)pCntI,
                                                x_item, sage_it_Wl, sage_it_Wr, sage_it_b,
                                                out_item, stats, n_item);
    bn_final_kernel<<<512, 256, 0, s1>>>(out_item, stats, 0, bn_item_g, bn_item_b, n_item);
    cudaEventRecord(eJoin, s1);

    // s0: student path
    cudaStreamWaitEvent(0, eY, 0);
    edge_agg_kernel<<<(e_r + 7) / 8, 256>>>((const float*)pY, responds_dst, responds_src,
                                            (float*)pAggY, (float*)pCntS, e_r);
    cudaStreamWaitEvent(0, eG, 0);
    edge_simple_kernel<<<(e_p + 7) / 8, 256>>>((const float*)pR, (const float*)pQ,
                                               preceeds_src, preceeds_dst, sc_b1,
                                               (float*)pH, (float*)pCntP, e_p);
    out_stu_tc<<<gb_stu, 256, DYN_SMEM>>>((const float*)pAggY, (const float*)pCntS,
                                          x_student, (const float*)pH, (const float*)pCntP,
                                          sage_st_Wr, sc_W2, sage_st_b, sc_b2,
                                          out_stu, stats, n_stu);
    bn_final_kernel<<<2048, 256>>>(out_stu, stats, 256, bn_stu_g, bn_stu_b, n_stu);

    // ---- join ----
    cudaStreamWaitEvent(0, eJoin, 0);
}

// round 6
// speedup vs baseline: 1.5079x; 1.0571x over previous
#include <cuda_runtime.h>
#include <math.h>

#define D 128
#define MAX_N_STU 100000
#define MAX_N_ITEM 20000
#define MAX_E_R 500000
#define MAX_E_P 300000
#define SA_STRIDE 132   // 128 + 4 pad: conflict-free fragment LDS
#define TILE_M 64       // A-tile rows per block (smem 101KB -> 2 blocks/SM)

// ---------------- scratch (device globals; no allocation allowed) ------------
__device__ float g_mean_item[(size_t)MAX_N_ITEM * D];   // mean_s x_student over responds
__device__ float g_meanY_stu[(size_t)MAX_N_STU * D];    // mean_i Y over rev_responds
__device__ float g_Y[(size_t)MAX_N_ITEM * D];           // x_item @ sage_st_Wl
__device__ float g_R[(size_t)MAX_N_STU * D];
__device__ float g_Q[(size_t)MAX_N_STU * D];
__device__ float g_Hmean[(size_t)MAX_N_STU * D];
__device__ float g_stats[4 * D];  // itemSum | itemSS | stuSum | stuSS

// CSR scratch
__device__ int g_deg_item[MAX_N_ITEM];
__device__ int g_rp_item[MAX_N_ITEM + 1];
__device__ int g_cur_item[MAX_N_ITEM];
__device__ int g_adj_item[MAX_E_R];
__device__ int g_deg_rs[MAX_N_STU];
__device__ int g_rp_rs[MAX_N_STU + 1];
__device__ int g_cur_rs[MAX_N_STU];
__device__ int g_adj_rs[MAX_E_R];
__device__ int g_deg_p[MAX_N_STU];
__device__ int g_rp_p[MAX_N_STU + 1];
__device__ int g_cur_p[MAX_N_STU];
__device__ int g_adj_p[MAX_E_P];

// ---------------- small zero (degrees + stats only) ----------------------------
__global__ void zero_small_kernel() {
    int i = blockIdx.x * blockDim.x + threadIdx.x;
    int stride = gridDim.x * blockDim.x;
    for (int x = i; x < MAX_N_STU; x += stride) {
        g_deg_rs[x] = 0;
        g_deg_p[x] = 0;
        if (x < MAX_N_ITEM) g_deg_item[x] = 0;
        if (x < 4 * D) g_stats[x] = 0.f;
    }
}

// ---------------- CSR build ---------------------------------------------------
__global__ void hist_kernel(const int* __restrict__ rsrc, const int* __restrict__ rdst,
                            int eR, const int* __restrict__ pdst, int eP) {
    int i = blockIdx.x * blockDim.x + threadIdx.x;
    if (i < eR) {
        atomicAdd(&g_deg_item[rdst[i]], 1);
        atomicAdd(&g_deg_rs[rsrc[i]], 1);
    }
    if (i < eP) atomicAdd(&g_deg_p[pdst[i]], 1);
}

__global__ __launch_bounds__(1024) void scan3_kernel(int n_item, int n_stu) {
    int n;
    int *deg, *rp, *cur;
    if (blockIdx.x == 0) { n = n_item; deg = g_deg_item; rp = g_rp_item; cur = g_cur_item; }
    else if (blockIdx.x == 1) { n = n_stu; deg = g_deg_rs; rp = g_rp_rs; cur = g_cur_rs; }
    else { n = n_stu; deg = g_deg_p; rp = g_rp_p; cur = g_cur_p; }

    __shared__ int warpSums[32];
    int chunk = (n + 1023) >> 10;
    int begin = min((int)threadIdx.x * chunk, n);
    int end = min(begin + chunk, n);
    int s = 0;
    for (int i = begin; i < end; i++) s += deg[i];
    int lane = threadIdx.x & 31, w = threadIdx.x >> 5;
    int v = s;
#pragma unroll
    for (int o = 1; o < 32; o <<= 1) {
        int t = __shfl_up_sync(0xffffffffu, v, o);
        if (lane >= o) v += t;
    }
    if (lane == 31) warpSums[w] = v;
    __syncthreads();
    if (w == 0) {
        int t = warpSums[lane];
#pragma unroll
        for (int o = 1; o < 32; o <<= 1) {
            int u = __shfl_up_sync(0xffffffffu, t, o);
            if (lane >= o) t += u;
        }
        warpSums[lane] = t;
    }
    __syncthreads();
    int excl = v - s + (w > 0 ? warpSums[w - 1] : 0);
    int run = excl;
    for (int i = begin; i < end; i++) {
        rp[i] = run;
        cur[i] = run;
        run += deg[i];
    }
    if (begin < n && end == n) rp[n] = run;
}

__global__ void fill_kernel(const int* __restrict__ rsrc, const int* __restrict__ rdst,
                            int eR, const int* __restrict__ psrc,
                            const int* __restrict__ pdst, int eP) {
    int i = blockIdx.x * blockDim.x + threadIdx.x;
    if (i < eR) {
        int s = rsrc[i], d = rdst[i];
        g_adj_item[atomicAdd(&g_cur_item[d], 1)] = s;
        g_adj_rs[atomicAdd(&g_cur_rs[s], 1)] = d;
    }
    if (i < eP) {
        g_adj_p[atomicAdd(&g_cur_p[pdst[i]], 1)] = psrc[i];
    }
}

// ---------------- CSR gather aggregation (warp/node, 4-way neighbor MLP) -------
__global__ void agg_gather_kernel(const float* __restrict__ X,
                                  const int* __restrict__ rp,
                                  const int* __restrict__ adj,
                                  float* __restrict__ out, int N) {
    int node = (blockIdx.x * blockDim.x + threadIdx.x) >> 5;
    if (node >= N) return;
    int lane = threadIdx.x & 31;
    int b = rp[node], e = rp[node + 1];
    float4 acc = make_float4(0.f, 0.f, 0.f, 0.f);
    int i = b;
    for (; i + 4 <= e; i += 4) {
        int n0 = __ldg(adj + i), n1 = __ldg(adj + i + 1);
        int n2 = __ldg(adj + i + 2), n3 = __ldg(adj + i + 3);
        float4 v0 = ((const float4*)(X + (size_t)n0 * D))[lane];
        float4 v1 = ((const float4*)(X + (size_t)n1 * D))[lane];
        float4 v2 = ((const float4*)(X + (size_t)n2 * D))[lane];
        float4 v3 = ((const float4*)(X + (size_t)n3 * D))[lane];
        acc.x += (v0.x + v1.x) + (v2.x + v3.x);
        acc.y += (v0.y + v1.y) + (v2.y + v3.y);
        acc.z += (v0.z + v1.z) + (v2.z + v3.z);
        acc.w += (v0.w + v1.w) + (v2.w + v3.w);
    }
    for (; i < e; i++) {
        int n = __ldg(adj + i);
        float4 v = ((const float4*)(X + (size_t)n * D))[lane];
        acc.x += v.x; acc.y += v.y; acc.z += v.z; acc.w += v.w;
    }
    float inv = 1.f / (float)max(e - b, 1);
    acc.x *= inv; acc.y *= inv; acc.z *= inv; acc.w *= inv;
    ((float4*)(out + (size_t)node * D))[lane] = acc;
}

__device__ __forceinline__ float elu1(float x) {
    return x > 0.f ? x : expm1f(x);
}

// Hmean[d] = mean_s elu(R[s] + Q[d] + b1)
__global__ void simple_gather_kernel(const float* __restrict__ R,
                                     const float* __restrict__ Q,
                                     const float* __restrict__ b1,
                                     const int* __restrict__ rp,
                                     const int* __restrict__ adj,
                                     float* __restrict__ Hmean, int N) {
    int node = (blockIdx.x * blockDim.x + threadIdx.x) >> 5;
    if (node >= N) return;
    int lane = threadIdx.x & 31;
    int b = rp[node], e = rp[node + 1];
    float4 qd = ((const float4*)(Q + (size_t)node * D))[lane];
    float4 bb = ((const float4*)b1)[lane];
    qd.x += bb.x; qd.y += bb.y; qd.z += bb.z; qd.w += bb.w;
    float4 acc = make_float4(0.f, 0.f, 0.f, 0.f);
    int i = b;
    for (; i + 4 <= e; i += 4) {
        int n0 = __ldg(adj + i), n1 = __ldg(adj + i + 1);
        int n2 = __ldg(adj + i + 2), n3 = __ldg(adj + i + 3);
        float4 v0 = ((const float4*)(R + (size_t)n0 * D))[lane];
        float4 v1 = ((const float4*)(R + (size_t)n1 * D))[lane];
        float4 v2 = ((const float4*)(R + (size_t)n2 * D))[lane];
        float4 v3 = ((const float4*)(R + (size_t)n3 * D))[lane];
        acc.x += elu1(v0.x + qd.x) + elu1(v1.x + qd.x) + elu1(v2.x + qd.x) + elu1(v3.x + qd.x);
        acc.y += elu1(v0.y + qd.y) + elu1(v1.y + qd.y) + elu1(v2.y + qd.y) + elu1(v3.y + qd.y);
        acc.z += elu1(v0.z + qd.z) + elu1(v1.z + qd.z) + elu1(v2.z + qd.z) + elu1(v3.z + qd.z);
        acc.w += elu1(v0.w + qd.w) + elu1(v1.w + qd.w) + elu1(v2.w + qd.w) + elu1(v3.w + qd.w);
    }
    for (; i < e; i++) {
        int n = __ldg(adj + i);
        float4 v = ((const float4*)(R + (size_t)n * D))[lane];
        acc.x += elu1(v.x + qd.x);
        acc.y += elu1(v.y + qd.y);
        acc.z += elu1(v.z + qd.z);
        acc.w += elu1(v.w + qd.w);
    }
    float inv = 1.f / (float)max(e - b, 1);
    acc.x *= inv; acc.y *= inv; acc.z *= inv; acc.w *= inv;
    ((float4*)(Hmean + (size_t)node * D))[lane] = acc;
}

// ---------------- tensor-core GEMM pieces (tf32 mma.sync) ---------------------
__device__ __forceinline__ unsigned f2tf(float x) {
    unsigned r;
    asm("cvt.rna.tf32.f32 %0, %1;" : "=r"(r) : "f"(x));
    return r;
}

__device__ __forceinline__ void stage_A(const float* __restrict__ A, int M,
                                        int rowBase, unsigned* sA) {
    for (int i = threadIdx.x; i < TILE_M * 32; i += 256) {
        int r = i >> 5, c4 = (i & 31) * 4;
        int gr = rowBase + r;
        float4 v = make_float4(0.f, 0.f, 0.f, 0.f);
        if (gr < M) v = ((const float4*)(A + (size_t)gr * D))[c4 >> 2];
        uint4 u;
        u.x = f2tf(v.x); u.y = f2tf(v.y); u.z = f2tf(v.z); u.w = f2tf(v.w);
        *(uint4*)(sA + r * SA_STRIDE + c4) = u;
    }
}

__device__ __forceinline__ void stage_Wt(const float* __restrict__ W, unsigned* sW) {
    for (int i = threadIdx.x; i < 128 * 32; i += 256) {
        int k = i & 127, n4 = i >> 7;
        float4 v = ((const float4*)(W + (size_t)k * D))[n4];
        sW[(n4 * 4 + 0) * SA_STRIDE + k] = f2tf(v.x);
        sW[(n4 * 4 + 1) * SA_STRIDE + k] = f2tf(v.y);
        sW[(n4 * 4 + 2) * SA_STRIDE + k] = f2tf(v.z);
        sW[(n4 * 4 + 3) * SA_STRIDE + k] = f2tf(v.w);
    }
}

__device__ __forceinline__ void stage_Wt_diff(const float* __restrict__ Wa,
                                              const float* __restrict__ Wb,
                                              unsigned* sW) {
    for (int i = threadIdx.x; i < 128 * 32; i += 256) {
        int k = i & 127, n4 = i >> 7;
        float4 a = ((const float4*)(Wa + (size_t)k * D))[n4];
        float4 b = ((const float4*)(Wb + (size_t)k * D))[n4];
        sW[(n4 * 4 + 0) * SA_STRIDE + k] = f2tf(a.x - b.x);
        sW[(n4 * 4 + 1) * SA_STRIDE + k] = f2tf(a.y - b.y);
        sW[(n4 * 4 + 2) * SA_STRIDE + k] = f2tf(a.z - b.z);
        sW[(n4 * 4 + 3) * SA_STRIDE + k] = f2tf(a.w - b.w);
    }
}

// m32n32 warp tile over 64x128 block tile.
__device__ __forceinline__ void mm_tc32(const unsigned* sA, const unsigned* sW,
                                        float acc[2][4][4]) {
    int lane = threadIdx.x & 31, w = threadIdx.x >> 5;
    int g = lane >> 2, t = lane & 3;
    int rg = w >> 2, cg = w & 3;
    const unsigned* A0 = sA + (rg * 32 + g) * SA_STRIDE + t;
    const unsigned* B0 = sW + (cg * 32 + g) * SA_STRIDE + t;
#pragma unroll
    for (int k0 = 0; k0 < 128; k0 += 8) {
        unsigned a[2][4];
#pragma unroll
        for (int mi = 0; mi < 2; mi++) {
            const unsigned* Ab = A0 + mi * 16 * SA_STRIDE + k0;
            a[mi][0] = Ab[0];
            a[mi][1] = Ab[8 * SA_STRIDE];
            a[mi][2] = Ab[4];
            a[mi][3] = Ab[8 * SA_STRIDE + 4];
        }
#pragma unroll
        for (int j = 0; j < 4; j++) {
            const unsigned* Bb = B0 + j * 8 * SA_STRIDE + k0;
            unsigned b0 = Bb[0], b1 = Bb[4];
#pragma unroll
            for (int mi = 0; mi < 2; mi++) {
                asm volatile(
                    "mma.sync.aligned.m16n8k8.row.col.f32.tf32.tf32.f32 "
                    "{%0,%1,%2,%3},{%4,%5,%6,%7},{%8,%9},{%0,%1,%2,%3};"
                    : "+f"(acc[mi][j][0]), "+f"(acc[mi][j][1]),
                      "+f"(acc[mi][j][2]), "+f"(acc[mi][j][3])
                    : "r"(a[mi][0]), "r"(a[mi][1]), "r"(a[mi][2]), "r"(a[mi][3]),
                      "r"(b0), "r"(b1));
            }
        }
    }
}

__device__ __forceinline__ void store_tile(float* __restrict__ C, int M, int rowBase,
                                           float acc[2][4][4]) {
    int lane = threadIdx.x & 31, w = threadIdx.x >> 5;
    int g = lane >> 2, t = lane & 3;
    int rg = w >> 2, cg = w & 3;
#pragma unroll
    for (int mi = 0; mi < 2; mi++) {
        int rA = rowBase + rg * 32 + mi * 16 + g, rB = rA + 8;
#pragma unroll
        for (int j = 0; j < 4; j++) {
            int c = cg * 32 + j * 8 + 2 * t;
            if (rA < M) *(float2*)(C + (size_t)rA * D + c) = make_float2(acc[mi][j][0], acc[mi][j][1]);
            if (rB < M) *(float2*)(C + (size_t)rB * D + c) = make_float2(acc[mi][j][2], acc[mi][j][3]);
        }
    }
}

// C = A @ W  (single mm)
__global__ __launch_bounds__(256, 2) void gemm_one_tc(const float* __restrict__ A,
                                                      const float* __restrict__ W,
                                                      float* __restrict__ C, int M) {
    extern __shared__ unsigned smem_u[];
    unsigned* sA = smem_u;
    unsigned* sW = smem_u + TILE_M * SA_STRIDE;
    int rowBase = blockIdx.x * TILE_M;
    float acc[2][4][4] = {};
    stage_A(A, M, rowBase, sA);
    stage_Wt(W, sW);
    __syncthreads();
    mm_tc32(sA, sW, acc);
    store_tile(C, M, rowBase, acc);
}

// R = x@(W1top - W1bot), Q = x@W1bot; shares the staged A tile.
__global__ __launch_bounds__(256, 2) void gemm_rq_tc(const float* __restrict__ x,
                                                     const float* __restrict__ W1,
                                                     float* __restrict__ Rm,
                                                     float* __restrict__ Qm, int M) {
    extern __shared__ unsigned smem_u[];
    unsigned* sA = smem_u;
    unsigned* sW = smem_u + TILE_M * SA_STRIDE;
    int rowBase = blockIdx.x * TILE_M;

    stage_A(x, M, rowBase, sA);
    stage_Wt(W1 + 128 * D, sW);
    __syncthreads();
    {
        float acc[2][4][4] = {};
        mm_tc32(sA, sW, acc);
        store_tile(Qm, M, rowBase, acc);
    }
    __syncthreads();
    stage_Wt_diff(W1, W1 + 128 * D, sW);
    __syncthreads();
    {
        float acc[2][4][4] = {};
        mm_tc32(sA, sW, acc);
        store_tile(Rm, M, rowBase, acc);
    }
}

// Shared epilogue helper: smem + global reduction of per-column sums.
__device__ __forceinline__ void stats_reduce(float* sred, const float lsum[8],
                                             const float lss[8], int cg, int t,
                                             float* __restrict__ statSum,
                                             float* __restrict__ statSS) {
    __syncthreads();
    sred[threadIdx.x] = 0.f;
    __syncthreads();
#pragma unroll
    for (int j = 0; j < 4; j++) {
        int c = cg * 32 + j * 8 + 2 * t;
        atomicAdd(&sred[c], lsum[2 * j]);
        atomicAdd(&sred[c + 1], lsum[2 * j + 1]);
        atomicAdd(&sred[128 + c], lss[2 * j]);
        atomicAdd(&sred[128 + c + 1], lss[2 * j + 1]);
    }
    __syncthreads();
    if (threadIdx.x < 128) {
        atomicAdd(statSum + threadIdx.x, sred[threadIdx.x]);
        atomicAdd(statSS + threadIdx.x, sred[128 + threadIdx.x]);
    }
}

// item pre-BN = elu( meanI@Wl + x_item@Wr + b ) -> out, + BN stats
__global__ __launch_bounds__(256, 2) void out_item_tc(
    const float* __restrict__ meanI, const float* __restrict__ x_item,
    const float* __restrict__ Wl, const float* __restrict__ Wr,
    const float* __restrict__ b, float* __restrict__ out,
    float* __restrict__ stats, int M) {
    extern __shared__ unsigned smem_u[];
    unsigned* sA = smem_u;
    unsigned* sW = smem_u + TILE_M * SA_STRIDE;
    int rowBase = blockIdx.x * TILE_M;
    float acc[2][4][4] = {};

    stage_A(meanI, M, rowBase, sA);
    stage_Wt(Wl, sW);
    __syncthreads();
    mm_tc32(sA, sW, acc);
    __syncthreads();
    stage_A(x_item, M, rowBase, sA);
    stage_Wt(Wr, sW);
    __syncthreads();
    mm_tc32(sA, sW, acc);

    int lane = threadIdx.x & 31, w = threadIdx.x >> 5;
    int g = lane >> 2, t = lane & 3;
    int rg = w >> 2, cg = w & 3;
    float lsum[8] = {}, lss[8] = {};
#pragma unroll
    for (int mi = 0; mi < 2; mi++) {
        int rA = rowBase + rg * 32 + mi * 16 + g, rB = rA + 8;
#pragma unroll
        for (int j = 0; j < 4; j++) {
            int c = cg * 32 + j * 8 + 2 * t;
            float b0v = b[c], b1v = b[c + 1];
            if (rA < M) {
                float e0 = elu1(acc[mi][j][0] + b0v);
                float e1 = elu1(acc[mi][j][1] + b1v);
                *(float2*)(out + (size_t)rA * D + c) = make_float2(e0, e1);
                lsum[2 * j] += e0; lss[2 * j] += e0 * e0;
                lsum[2 * j + 1] += e1; lss[2 * j + 1] += e1 * e1;
            }
            if (rB < M) {
                float e2 = elu1(acc[mi][j][2] + b0v);
                float e3 = elu1(acc[mi][j][3] + b1v);
                *(float2*)(out + (size_t)rB * D + c) = make_float2(e2, e3);
                lsum[2 * j] += e2; lss[2 * j] += e2 * e2;
                lsum[2 * j + 1] += e3; lss[2 * j + 1] += e3 * e3;
            }
        }
    }
    stats_reduce((float*)sA, lsum, lss, cg, t, stats + 0, stats + 128);
}

// stu pre-BN = elu( 0.5*( meanY + x@Wr + b_st + Hmean@W2 + [deg>0]*b2 ) )
__global__ __launch_bounds__(256, 2) void out_stu_tc(
    const float* __restrict__ meanY, const float* __restrict__ x_stu,
    const float* __restrict__ Hmean, const int* __restrict__ degP,
    const float* __restrict__ Wr, const float* __restrict__ W2,
    const float* __restrict__ b_st, const float* __restrict__ b2,
    float* __restrict__ out, float* __restrict__ stats, int M) {
    extern __shared__ unsigned smem_u[];
    unsigned* sA = smem_u;
    unsigned* sW = smem_u + TILE_M * SA_STRIDE;
    int rowBase = blockIdx.x * TILE_M;
    float acc[2][4][4] = {};

    stage_A(x_stu, M, rowBase, sA);
    stage_Wt(Wr, sW);
    __syncthreads();
    mm_tc32(sA, sW, acc);
    __syncthreads();
    stage_A(Hmean, M, rowBase, sA);
    stage_Wt(W2, sW);
    __syncthreads();
    mm_tc32(sA, sW, acc);

    int lane = threadIdx.x & 31, w = threadIdx.x >> 5;
    int g = lane >> 2, t = lane & 3;
    int rg = w >> 2, cg = w & 3;
    float lsum[8] = {}, lss[8] = {};
#pragma unroll
    for (int mi = 0; mi < 2; mi++) {
        int rA = rowBase + rg * 32 + mi * 16 + g, rB = rA + 8;
        float hA = (rA < M && degP[rA] > 0) ? 1.f : 0.f;
        float hB = (rB < M && degP[rB] > 0) ? 1.f : 0.f;
#pragma unroll
        for (int j = 0; j < 4; j++) {
            int c = cg * 32 + j * 8 + 2 * t;
            float bs0 = b_st[c], bs1 = b_st[c + 1];
            float b20 = b2[c], b21 = b2[c + 1];
            if (rA < M) {
                float2 y = *(const float2*)(meanY + (size_t)rA * D + c);
                float e0 = elu1(0.5f * (acc[mi][j][0] + y.x + bs0 + hA * b20));
                float e1 = elu1(0.5f * (acc[mi][j][1] + y.y + bs1 + hA * b21));
                *(float2*)(out + (size_t)rA * D + c) = make_float2(e0, e1);
                lsum[2 * j] += e0; lss[2 * j] += e0 * e0;
                lsum[2 * j + 1] += e1; lss[2 * j + 1] += e1 * e1;
            }
            if (rB < M) {
                float2 y = *(const float2*)(meanY + (size_t)rB * D + c);
                float e2 = elu1(0.5f * (acc[mi][j][2] + y.x + bs0 + hB * b20));
                float e3 = elu1(0.5f * (acc[mi][j][3] + y.y + bs1 + hB * b21));
                *(float2*)(out + (size_t)rB * D + c) = make_float2(e2, e3);
                lsum[2 * j] += e2; lss[2 * j] += e2 * e2;
                lsum[2 * j + 1] += e3; lss[2 * j + 1] += e3 * e3;
            }
        }
    }
    stats_reduce((float*)sA, lsum, lss, cg, t, stats + 256, stats + 384);
}

// ---------------- batch-norm finalize -----------------------------------------
__global__ void bn_final_kernel(float* __restrict__ x,
                                const float* __restrict__ stats, int statOff,
                                const float* __restrict__ g,
                                const float* __restrict__ beta, int N) {
    __shared__ float sScale[128], sShift[128];
    if (threadIdx.x < 128) {
        int j = threadIdx.x;
        float invN = 1.f / (float)N;
        float mu = stats[statOff + j] * invN;
        float var = fmaxf(stats[statOff + 128 + j] * invN - mu * mu, 0.f);
        float sc = g[j] * rsqrtf(var + 1e-5f);
        sScale[j] = sc;
        sShift[j] = beta[j] - mu * sc;
    }
    __syncthreads();
    size_t total = (size_t)N * 32;
    size_t i = blockIdx.x * (size_t)blockDim.x + threadIdx.x;
    size_t stride = (size_t)gridDim.x * blockDim.x;
    float4* x4 = (float4*)x;
    for (; i < total; i += stride) {
        int j = ((int)i & 31) * 4;
        float4 v = x4[i];
        v.x = v.x * sScale[j + 0] + sShift[j + 0];
        v.y = v.y * sScale[j + 1] + sShift[j + 1];
        v.z = v.z * sScale[j + 2] + sShift[j + 2];
        v.w = v.w * sScale[j + 3] + sShift[j + 3];
        x4[i] = v;
    }
}

// ---------------- launch -------------------------------------------------------
extern "C" void kernel_launch(void* const* d_in, const int* in_sizes, int n_in,
                              void* d_out, int out_size) {
    const float* x_student = (const float*)d_in[0];
    const float* x_item = (const float*)d_in[1];
    const int* responds_src = (const int*)d_in[2];
    const int* responds_dst = (const int*)d_in[3];
    const int* preceeds_src = (const int*)d_in[4];
    const int* preceeds_dst = (const int*)d_in[5];
    const float* sage_it_Wl = (const float*)d_in[6];
    const float* sage_it_Wr = (const float*)d_in[7];
    const float* sage_it_b = (const float*)d_in[8];
    const float* sage_st_Wl = (const float*)d_in[9];
    const float* sage_st_Wr = (const float*)d_in[10];
    const float* sage_st_b = (const float*)d_in[11];
    const float* sc_W1 = (const float*)d_in[12];
    const float* sc_b1 = (const float*)d_in[13];
    const float* sc_W2 = (const float*)d_in[14];
    const float* sc_b2 = (const float*)d_in[15];
    const float* bn_item_g = (const float*)d_in[16];
    const float* bn_item_b = (const float*)d_in[17];
    const float* bn_stu_g = (const float*)d_in[18];
    const float* bn_stu_b = (const float*)d_in[19];

    int n_stu = in_sizes[0] / D;
    int n_item = in_sizes[1] / D;
    int e_r = in_sizes[2];
    int e_p = in_sizes[4];

    const int DYN_SMEM = (TILE_M + 128) * SA_STRIDE * 4;  // 101376 B

    static cudaStream_t s1 = nullptr;
    static cudaEvent_t eStart, eY, eG, eAI, eJoin;
    if (s1 == nullptr) {
        cudaStreamCreateWithFlags(&s1, cudaStreamNonBlocking);
        cudaEventCreateWithFlags(&eStart, cudaEventDisableTiming);
        cudaEventCreateWithFlags(&eY, cudaEventDisableTiming);
        cudaEventCreateWithFlags(&eG, cudaEventDisableTiming);
        cudaEventCreateWithFlags(&eAI, cudaEventDisableTiming);
        cudaEventCreateWithFlags(&eJoin, cudaEventDisableTiming);
        cudaFuncSetAttribute(gemm_one_tc, cudaFuncAttributeMaxDynamicSharedMemorySize, DYN_SMEM);
        cudaFuncSetAttribute(gemm_rq_tc, cudaFuncAttributeMaxDynamicSharedMemorySize, DYN_SMEM);
        cudaFuncSetAttribute(out_item_tc, cudaFuncAttributeMaxDynamicSharedMemorySize, DYN_SMEM);
        cudaFuncSetAttribute(out_stu_tc, cudaFuncAttributeMaxDynamicSharedMemorySize, DYN_SMEM);
    }

    void *pMeanI, *pMeanY, *pY, *pR, *pQ, *pH, *pStats;
    void *pRpItem, *pAdjItem, *pRpRs, *pAdjRs, *pRpP, *pAdjP, *pDegP;
    cudaGetSymbolAddress(&pMeanI, g_mean_item);
    cudaGetSymbolAddress(&pMeanY, g_meanY_stu);
    cudaGetSymbolAddress(&pY, g_Y);
    cudaGetSymbolAddress(&pR, g_R);
    cudaGetSymbolAddress(&pQ, g_Q);
    cudaGetSymbolAddress(&pH, g_Hmean);
    cudaGetSymbolAddress(&pStats, g_stats);
    cudaGetSymbolAddress(&pRpItem, g_rp_item);
    cudaGetSymbolAddress(&pAdjItem, g_adj_item);
    cudaGetSymbolAddress(&pRpRs, g_rp_rs);
    cudaGetSymbolAddress(&pAdjRs, g_adj_rs);
    cudaGetSymbolAddress(&pRpP, g_rp_p);
    cudaGetSymbolAddress(&pAdjP, g_adj_p);
    cudaGetSymbolAddress(&pDegP, g_deg_p);

    float* out = (float*)d_out;
    float* out_item = out;
    float* out_stu = out + (size_t)n_item * D;
    float* stats = (float*)pStats;

    int maxE = max(e_r, e_p);
    int gb_stu = (n_stu + TILE_M - 1) / TILE_M;
    int gb_item = (n_item + TILE_M - 1) / TILE_M;

    // ---- fork: s1 runs projection GEMMs while s0 builds CSR ----
    cudaEventRecord(eStart, 0);
    cudaStreamWaitEvent(s1, eStart, 0);

    // s1: Y = x_item @ sage_st_Wl ; R/Q projections
    gemm_one_tc<<<gb_item, 256, DYN_SMEM, s1>>>(x_item, sage_st_Wl, (float*)pY, n_item);
    cudaEventRecord(eY, s1);
    gemm_rq_tc<<<gb_stu, 256, DYN_SMEM, s1>>>(x_student, sc_W1, (float*)pR, (float*)pQ, n_stu);
    cudaEventRecord(eG, s1);

    // s0: CSR build (independent of GEMMs)
    zero_small_kernel<<<256, 256>>>();
    hist_kernel<<<(maxE + 255) / 256, 256>>>(responds_src, responds_dst, e_r,
                                             preceeds_dst, e_p);
    scan3_kernel<<<3, 1024>>>(n_item, n_stu);
    fill_kernel<<<(maxE + 255) / 256, 256>>>(responds_src, responds_dst, e_r,
                                             preceeds_src, preceeds_dst, e_p);

    // s0: item-side aggregation (needs CSR only)
    agg_gather_kernel<<<(n_item * 32 + 255) / 256, 256>>>(
        x_student, (const int*)pRpItem, (const int*)pAdjItem, (float*)pMeanI, n_item);
    cudaEventRecord(eAI, 0);

    // s1: item output path (needs meanI + zeroed stats)
    cudaStreamWaitEvent(s1, eAI, 0);
    out_item_tc<<<gb_item, 256, DYN_SMEM, s1>>>((const float*)pMeanI, x_item,
                                                sage_it_Wl, sage_it_Wr, sage_it_b,
                                                out_item, stats, n_item);
    bn_final_kernel<<<512, 256, 0, s1>>>(out_item, stats, 0, bn_item_g, bn_item_b, n_item);
    cudaEventRecord(eJoin, s1);

    // s0: student path
    cudaStreamWaitEvent(0, eY, 0);
    agg_gather_kernel<<<(n_stu * 32 + 255) / 256, 256>>>(
        (const float*)pY, (const int*)pRpRs, (const int*)pAdjRs, (float*)pMeanY, n_stu);
    cudaStreamWaitEvent(0, eG, 0);
    simple_gather_kernel<<<(n_stu * 32 + 255) / 256, 256>>>(
        (const float*)pR, (const float*)pQ, sc_b1, (const int*)pRpP,
        (const int*)pAdjP, (float*)pH, n_stu);
    out_stu_tc<<<gb_stu, 256, DYN_SMEM>>>((const float*)pMeanY, x_student,
                                          (const float*)pH, (const int*)pDegP,
                                          sage_st_Wr, sc_W2, sage_st_b, sc_b2,
                                          out_stu, stats, n_stu);
    bn_final_kernel<<<2048, 256>>>(out_stu, stats, 256, bn_stu_g, bn_stu_b, n_stu);

    // ---- join ----
    cudaStreamWaitEvent(0, eJoin, 0);
}